// round 12
// baseline (speedup 1.0000x reference)
#include <cuda_runtime.h>
#include <cuda_fp16.h>
#include <math.h>
#include <stdint.h>

// Problem constants
#define BATCH 8
#define SQ    1024
#define SK    1024
#define DM    512
#define NH    8
#define HALF  4                                   // batches per pipeline half

// ---------------- device scratch ----------------------------------------------
__device__ __half g_Qh[BATCH * SQ * DM];
__device__ __half g_Kh[BATCH * SK * DM];
__device__ __half g_Vh[BATCH * SK * DM];
__device__ __half g_Wqh[DM * DM];
__device__ __half g_Wkh[DM * DM];
__device__ __half g_Wvh[DM * DM];
__device__ __half g_M[DM * DM];              // M~ = Wq @ Wk^T (fp16)
__device__ __half g_Km[BATCH * SK * DM];     // K @ M~^T per batch
__device__ __half g_VWt[BATCH * DM * SK];    // (V @ Wc)^T per batch: [b][d][sk]
__device__ float  g_att[BATCH * SQ * SK];    // fp32 scores
__device__ __half g_att_h[BATCH * SQ * SK];  // fp16 probs (final GEMM A)
__device__ __half g_WleT[DM * DM];
__device__ __half g_WcT[DM * DM];
__device__ __half g_WcP[4 * DM * DM];        // shared split-K partials (M~ then WcT)
__device__ float  g_bc[DM];
__device__ float  g_wqbk[DM];
__device__ float  g_wkbq[DM];
__device__ float  g_a[BATCH * SQ];           // row bias for scores
__device__ float  g_b[BATCH * SK];           // col bias for scores
__device__ float  g_c[1];
__device__ float  g_zero = 0.f;              // never written

// ---------------- PTX helpers --------------------------------------------------
__device__ __forceinline__ uint32_t smem_u32(const void* p) {
    uint32_t a;
    asm("{ .reg .u64 t; cvta.to.shared.u64 t, %1; cvt.u32.u64 %0, t; }" : "=r"(a) : "l"(p));
    return a;
}

#define CP_ASYNC16(dst, src) \
    asm volatile("cp.async.cg.shared.global [%0], [%1], 16;" :: "r"(dst), "l"(src) : "memory")
#define CP_COMMIT() asm volatile("cp.async.commit_group;" ::: "memory")
#define CP_WAIT2()  asm volatile("cp.async.wait_group 2;" ::: "memory")
#define CP_WAIT1()  asm volatile("cp.async.wait_group 1;" ::: "memory")
#define CP_WAIT0()  asm volatile("cp.async.wait_group 0;" ::: "memory")

#define LDSM4(r0, r1, r2, r3, addr) \
    asm volatile("ldmatrix.sync.aligned.m8n8.x4.shared.b16 {%0,%1,%2,%3}, [%4];" \
        : "=r"(r0), "=r"(r1), "=r"(r2), "=r"(r3) : "r"(addr))

__device__ __forceinline__ void mma_f16(float* c, const uint32_t* a, const uint32_t* b) {
    asm volatile(
        "mma.sync.aligned.m16n8k16.row.col.f32.f16.f16.f32 "
        "{%0,%1,%2,%3}, {%4,%5,%6,%7}, {%8,%9}, {%0,%1,%2,%3};"
        : "+f"(c[0]), "+f"(c[1]), "+f"(c[2]), "+f"(c[3])
        : "r"(a[0]), "r"(a[1]), "r"(a[2]), "r"(a[3]), "r"(b[0]), "r"(b[1]));
}

// ================================================================================
// fp16 mma.sync GEMM: C[M,N] = A[M,K] @ B[N,K]^T   (fp32 accumulate)
// Block tile 256x128x32, 8 warps (4x2), warp tile 64x64, 3-stage cp.async ring,
// ldmatrix.x4 fragment loads (conflict-free with LDH=40 stride).
// MODE 0: C += bias[n]; output fp16 if OUT_HALF else fp32
// MODE 1: C = C*scale + rowb[bz*SQ+m] + colb[bz*SK+n] + mask[bz][n]*-1e9 (fp32 out)
// MODE 2: transposed fp16 store: out[b2*foldT + n*ldT + mloc]
// grid (N/128, M/256, batches-or-ksplits), 256 threads
// ================================================================================
#define BM 256
#define BN 128
#define BK 32
#define LDH 40
#define A_TILE_H (BM * LDH)                      // 10240
#define B_TILE_H (BN * LDH)                      // 5120
#define STAGE_H  (A_TILE_H + B_TILE_H)           // 15360
#define NSTAGE 3
#define GEMM_SMEM (NSTAGE * STAGE_H * 2)         // 92160 B

template <int MODE, int OUT_HALF>
__global__ void __launch_bounds__(256, 1) gemm_h(
    const __half* __restrict__ A, const __half* __restrict__ B, void* __restrict__ Cv,
    int Kdim, long sA, long sB, long sC,
    const float* __restrict__ bias, const int* __restrict__ mask, float scale,
    int ldT, long foldT, int lda, int ldb,
    const float* __restrict__ rowb, const float* __restrict__ colb)
{
    extern __shared__ __half smem[];
    const uint32_t smb = smem_u32(smem);

    const int tid = threadIdx.x;
    const int lane = tid & 31, wid = tid >> 5;
    const int g = lane >> 2, t = lane & 3;
    const int wm = wid >> 1, wn = wid & 1;       // 4 x 2 warps, warp tile 64x64
    const int m0 = blockIdx.y * BM, n0 = blockIdx.x * BN, bz = blockIdx.z;

    const __half* Ag = A + (long)bz * sA;
    const __half* Bg = B + (long)bz * sB;

    float acc[4][8][4];
#pragma unroll
    for (int i = 0; i < 4; i++)
#pragma unroll
        for (int j = 0; j < 8; j++)
#pragma unroll
            for (int r = 0; r < 4; r++) acc[i][j][r] = 0.f;

    const int NC = Kdim / BK;
    const int lrow = tid >> 2, lchunk = (tid & 3) * 8;   // cp.async slots

    const int lj = lane >> 3, lr8 = lane & 7;
    uint32_t aoff[4], boff[4];
#pragma unroll
    for (int mt = 0; mt < 4; mt++)
        aoff[mt] = (uint32_t)(((wm * 64 + mt * 16 + lr8 + 8 * (lj & 1)) * LDH
                               + 8 * (lj >> 1)) * 2);
#pragma unroll
    for (int np = 0; np < 4; np++)
        boff[np] = (uint32_t)((A_TILE_H + (wn * 64 + np * 16 + lr8 + 8 * (lj >> 1)) * LDH
                               + 8 * (lj & 1)) * 2);

    auto issue = [&](int c, int s) {
        const long k0 = (long)c * BK;
        const uint32_t abase = smb + (uint32_t)(s * STAGE_H * 2);
        const uint32_t bbase = abase + (uint32_t)(A_TILE_H * 2);
#pragma unroll
        for (int j = 0; j < 4; j++) {
            int row = lrow + 64 * j;
            CP_ASYNC16(abase + (uint32_t)((row * LDH + lchunk) * 2),
                       Ag + (long)(m0 + row) * lda + k0 + lchunk);
        }
#pragma unroll
        for (int j = 0; j < 2; j++) {
            int row = lrow + 64 * j;
            CP_ASYNC16(bbase + (uint32_t)((row * LDH + lchunk) * 2),
                       Bg + (long)(n0 + row) * ldb + k0 + lchunk);
        }
        CP_COMMIT();
    };

    issue(0, 0);
    if (NC > 1) issue(1, 1);

    for (int c = 0; c < NC; c++) {
        const int buf = c % NSTAGE;
        if (c + 2 < NC) { issue(c + 2, (c + 2) % NSTAGE); CP_WAIT2(); }
        else if (c + 1 < NC) { CP_WAIT1(); }
        else { CP_WAIT0(); }
        __syncthreads();

        const uint32_t sbase = smb + (uint32_t)(buf * STAGE_H * 2);

#pragma unroll
        for (int kk = 0; kk < 2; kk++) {
            const uint32_t kboff = (uint32_t)(kk * 16 * 2);
            uint32_t af[4][4], bf[8][2];
#pragma unroll
            for (int mt = 0; mt < 4; mt++)
                LDSM4(af[mt][0], af[mt][1], af[mt][2], af[mt][3],
                      sbase + aoff[mt] + kboff);
#pragma unroll
            for (int np = 0; np < 4; np++)
                LDSM4(bf[2 * np][0], bf[2 * np][1], bf[2 * np + 1][0], bf[2 * np + 1][1],
                      sbase + boff[np] + kboff);
#pragma unroll
            for (int mt = 0; mt < 4; mt++)
#pragma unroll
                for (int nt = 0; nt < 8; nt++)
                    mma_f16(acc[mt][nt], af[mt], bf[nt]);
        }
        __syncthreads();
    }

    // ---- epilogue ----
    if (MODE == 2) {
        __half* Cz = (__half*)Cv + (long)bz * sC;
        __half* stage = smem;                    // [128][264] halves (n x m)
#pragma unroll
        for (int mt = 0; mt < 4; mt++) {
            const int r0 = wm * 64 + mt * 16 + g;
#pragma unroll
            for (int nt = 0; nt < 8; nt++) {
                const int c0 = wn * 64 + nt * 8 + t * 2;
                stage[(c0    ) * 264 + r0    ] = __float2half_rn(acc[mt][nt][0]);
                stage[(c0 + 1) * 264 + r0    ] = __float2half_rn(acc[mt][nt][1]);
                stage[(c0    ) * 264 + r0 + 8] = __float2half_rn(acc[mt][nt][2]);
                stage[(c0 + 1) * 264 + r0 + 8] = __float2half_rn(acc[mt][nt][3]);
            }
        }
        __syncthreads();
        const int b2 = m0 >> 10, mq = tid & 63, rq = tid >> 6;
        const int mloc = (m0 & 1023) + mq * 4;
#pragma unroll
        for (int it = 0; it < 32; it++) {
            const int nr = rq + it * 4;
            uint2 v = *(const uint2*)&stage[nr * 264 + mq * 4];
            *(uint2*)&Cz[(long)b2 * foldT + (long)(n0 + nr) * ldT + mloc] = v;
        }
        return;
    }

    const int ldc = gridDim.x * BN;
#pragma unroll
    for (int mt = 0; mt < 4; mt++) {
        const int r0 = m0 + wm * 64 + mt * 16 + g;
#pragma unroll
        for (int nt = 0; nt < 8; nt++) {
            const int c0 = n0 + wn * 64 + nt * 8 + t * 2;
            float2 v0 = { acc[mt][nt][0], acc[mt][nt][1] };
            float2 v1 = { acc[mt][nt][2], acc[mt][nt][3] };
            if (MODE == 0) {
                if (bias) {
                    v0.x += bias[c0]; v0.y += bias[c0 + 1];
                    v1.x += bias[c0]; v1.y += bias[c0 + 1];
                }
                if (OUT_HALF) {
                    __half* Cg = (__half*)Cv + (long)bz * sC;
                    *(__half2*)&Cg[(long)r0 * ldc + c0]       = __floats2half2_rn(v0.x, v0.y);
                    *(__half2*)&Cg[(long)(r0 + 8) * ldc + c0] = __floats2half2_rn(v1.x, v1.y);
                    continue;
                }
            } else { // MODE 1: scale + row/col rank-1 bias + mask
                const int* mk = mask + (long)bz * SK;
                float p0 = mk[c0] ? -1e9f : 0.f, p1 = mk[c0 + 1] ? -1e9f : 0.f;
                float ra  = rowb[(long)bz * SQ + r0];
                float ra8 = rowb[(long)bz * SQ + r0 + 8];
                float cb0 = colb[(long)bz * SK + c0];
                float cb1 = colb[(long)bz * SK + c0 + 1];
                v0.x = v0.x * scale + ra  + cb0 + p0; v0.y = v0.y * scale + ra  + cb1 + p1;
                v1.x = v1.x * scale + ra8 + cb0 + p0; v1.y = v1.y * scale + ra8 + cb1 + p1;
            }
            float* Cg = (float*)Cv + (long)bz * sC;
            *(float2*)&Cg[(long)r0 * ldc + c0]       = v0;
            *(float2*)&Cg[(long)(r0 + 8) * ldc + c0] = v1;
        }
    }
}

// ================================================================================
// helper kernels
// ================================================================================
__global__ void f32_to_f16(const float* __restrict__ in, __half* __restrict__ out) {
    long i = ((long)blockIdx.x * 256 + threadIdx.x) * 4;
    float4 v = *(const float4*)&in[i];
    __half2 h0 = __floats2half2_rn(v.x, v.y);
    __half2 h1 = __floats2half2_rn(v.z, v.w);
    uint2 p = { *(uint32_t*)&h0, *(uint32_t*)&h1 };
    *(uint2*)&out[i] = p;
}

__global__ void wl_sumT_tiled(const float* __restrict__ Wl, __half* __restrict__ WleT) {
    __shared__ float t[32][33];
    int bx = blockIdx.x * 32, by = blockIdx.y * 32;
    for (int i = threadIdx.y; i < 32; i += 8) {
        float s = 0.f;
#pragma unroll
        for (int h = 0; h < NH; h++)
            s += Wl[((long)(h * DM) + by + i) * DM + bx + threadIdx.x];
        t[i][threadIdx.x] = s;
    }
    __syncthreads();
    for (int i = threadIdx.y; i < 32; i += 8)
        WleT[(bx + i) * DM + by + threadIdx.x] = __float2half_rn(t[threadIdx.x][i]);
}

__global__ void bc_kernel(const float* __restrict__ bl, const float* __restrict__ bv,
                          const __half* __restrict__ WleT, float* __restrict__ bc) {
    const int n = blockIdx.x, t = threadIdx.x;
    __shared__ float red[256];
    float s = 0.f;
    for (int k = t; k < DM; k += 256) s += bv[k] * __half2float(WleT[n * DM + k]);
    red[t] = s;
    __syncthreads();
#pragma unroll
    for (int o = 128; o >= 32; o >>= 1) {
        if (t < o) red[t] += red[t + o];
        __syncthreads();
    }
    if (t < 32) {
        float v = red[t];
#pragma unroll
        for (int o = 16; o > 0; o >>= 1)
            v += __shfl_down_sync(0xffffffffu, v, o);
        if (t == 0) bc[n] = bl[n] + v;
    }
}

__global__ void dot512(const float* __restrict__ a, const float* __restrict__ b,
                       float* __restrict__ out) {
    const int t = threadIdx.x;
    __shared__ float red[256];
    float s = 0.f;
    for (int k = t; k < DM; k += 256) s += a[k] * b[k];
    red[t] = s;
    __syncthreads();
#pragma unroll
    for (int o = 128; o >= 32; o >>= 1) {
        if (t < o) red[t] += red[t + o];
        __syncthreads();
    }
    if (t < 32) {
        float v = red[t];
#pragma unroll
        for (int o = 16; o > 0; o >>= 1)
            v += __shfl_down_sync(0xffffffffu, v, o);
        if (t == 0) out[0] = v;
    }
}

__global__ void vecdot512(const float* __restrict__ W, const float* __restrict__ v,
                          float* __restrict__ out) {
    const int f = blockIdx.x, t = threadIdx.x;
    __shared__ float red[128];
    float s = 0.f;
    for (int k = t; k < DM; k += 128) s += W[(long)f * DM + k] * v[k];
    red[t] = s;
    __syncthreads();
#pragma unroll
    for (int o = 64; o >= 32; o >>= 1) {
        if (t < o) red[t] += red[t + o];
        __syncthreads();
    }
    if (t < 32) {
        float x = red[t];
#pragma unroll
        for (int o = 16; o > 0; o >>= 1)
            x += __shfl_down_sync(0xffffffffu, x, o);
        if (t == 0) out[f] = x;
    }
}

__global__ void rowdot(const float* __restrict__ X, const float* __restrict__ vec,
                       const float* __restrict__ cadd, float* __restrict__ out,
                       float scale) {
    const int r = blockIdx.x, t = threadIdx.x;
    __shared__ float red[128];
    float s = 0.f;
    for (int k = t; k < DM; k += 128) s += X[(long)r * DM + k] * vec[k];
    red[t] = s;
    __syncthreads();
#pragma unroll
    for (int o = 64; o >= 32; o >>= 1) {
        if (t < o) red[t] += red[t + o];
        __syncthreads();
    }
    if (t < 32) {
        float x = red[t];
#pragma unroll
        for (int o = 16; o > 0; o >>= 1)
            x += __shfl_down_sync(0xffffffffu, x, o);
        if (t == 0) out[r] = (x + cadd[0]) * scale;
    }
}

__global__ void reduce4(const __half* __restrict__ p, __half* __restrict__ o) {
    long i = ((long)blockIdx.x * 256 + threadIdx.x) * 4;
    float s[4];
#pragma unroll
    for (int j = 0; j < 4; j++) s[j] = 0.f;
#pragma unroll
    for (int part = 0; part < 4; part++) {
        uint2 v = *(const uint2*)&p[(long)part * DM * DM + i];
        __half2 h0 = *(__half2*)&v.x, h1 = *(__half2*)&v.y;
        s[0] += __low2float(h0);  s[1] += __high2float(h0);
        s[2] += __low2float(h1);  s[3] += __high2float(h1);
    }
    __half2 r0 = __floats2half2_rn(s[0], s[1]);
    __half2 r1 = __floats2half2_rn(s[2], s[3]);
    uint2 r = { *(uint32_t*)&r0, *(uint32_t*)&r1 };
    *(uint2*)&o[i] = r;
}

// fused softmax over grid (SQ, nb); bases pre-offset per half
__global__ void softmax_head0(const float* __restrict__ att, __half* __restrict__ att_h,
                              float* __restrict__ out_att) {
    const int q = blockIdx.x, b = blockIdx.y, t = threadIdx.x;
    const float* row = att + ((long)(b * SQ + q)) * SK;
    float4 v = ((const float4*)row)[t];

    __shared__ float red[256];
    float m = fmaxf(fmaxf(v.x, v.y), fmaxf(v.z, v.w));
    red[t] = m;
    __syncthreads();
#pragma unroll
    for (int s = 128; s > 0; s >>= 1) {
        if (t < s) red[t] = fmaxf(red[t], red[t + s]);
        __syncthreads();
    }
    m = red[0];
    __syncthreads();

    float4 e;
    e.x = expf(v.x - m); e.y = expf(v.y - m);
    e.z = expf(v.z - m); e.w = expf(v.w - m);
    red[t] = e.x + e.y + e.z + e.w;
    __syncthreads();
#pragma unroll
    for (int s = 128; s > 0; s >>= 1) {
        if (t < s) red[t] += red[t + s];
        __syncthreads();
    }
    float inv = 1.0f / red[0];
    e.x *= inv; e.y *= inv; e.z *= inv; e.w *= inv;

    __half2 h0 = __floats2half2_rn(e.x, e.y);
    __half2 h1 = __floats2half2_rn(e.z, e.w);
    uint2 ph = { *(uint32_t*)&h0, *(uint32_t*)&h1 };
    ((uint2*)(att_h + ((long)(b * SQ + q)) * SK))[t] = ph;

    if (out_att)
        ((float4*)(out_att + (((long)(b * NH) * SQ) + q) * SK))[t] = e;
}

// copy replica 0 -> replicas 1..7; base pre-offset per half
__global__ void replicate7(float* __restrict__ out_att) {
    const int q = blockIdx.x, b = blockIdx.y, t = threadIdx.x;
    const float4* src = (const float4*)(out_att + (((long)(b * NH) * SQ) + q) * SK);
    float4 v = src[t];
#pragma unroll
    for (int h = 1; h < NH; h++)
        ((float4*)(out_att + (((long)(b * NH + h) * SQ) + q) * SK))[t] = v;
}

// ================================================================================
// launch — batch-halved pipeline across 3 streams (graph-capturable)
// ================================================================================
extern "C" void kernel_launch(void* const* d_in, const int* in_sizes, int n_in,
                              void* d_out, int out_size) {
    const float* Q    = (const float*)d_in[0];
    const float* K    = (const float*)d_in[1];
    const float* V    = (const float*)d_in[2];
    const int*   mask = (const int*)  d_in[3];
    const float* Wq   = (const float*)d_in[4];
    const float* bq   = (const float*)d_in[5];
    const float* Wk   = (const float*)d_in[6];
    const float* bk   = (const float*)d_in[7];
    const float* Wv   = (const float*)d_in[8];
    const float* bv   = (const float*)d_in[9];
    const float* Wl   = (const float*)d_in[10];
    const float* bl   = (const float*)d_in[11];

    __half *Qh, *Kh, *Vh, *Wqh, *Wkh, *Wvh, *Mh, *Km, *VWt, *att_h, *wleT, *wcT, *wcP;
    float *att, *bc, *wqbk, *wkbq, *av, *bvv, *cs, *zs;
    cudaGetSymbolAddress((void**)&Qh,    g_Qh);
    cudaGetSymbolAddress((void**)&Kh,    g_Kh);
    cudaGetSymbolAddress((void**)&Vh,    g_Vh);
    cudaGetSymbolAddress((void**)&Wqh,   g_Wqh);
    cudaGetSymbolAddress((void**)&Wkh,   g_Wkh);
    cudaGetSymbolAddress((void**)&Wvh,   g_Wvh);
    cudaGetSymbolAddress((void**)&Mh,    g_M);
    cudaGetSymbolAddress((void**)&Km,    g_Km);
    cudaGetSymbolAddress((void**)&VWt,   g_VWt);
    cudaGetSymbolAddress((void**)&att,   g_att);
    cudaGetSymbolAddress((void**)&att_h, g_att_h);
    cudaGetSymbolAddress((void**)&wleT,  g_WleT);
    cudaGetSymbolAddress((void**)&wcT,   g_WcT);
    cudaGetSymbolAddress((void**)&wcP,   g_WcP);
    cudaGetSymbolAddress((void**)&bc,    g_bc);
    cudaGetSymbolAddress((void**)&wqbk,  g_wqbk);
    cudaGetSymbolAddress((void**)&wkbq,  g_wkbq);
    cudaGetSymbolAddress((void**)&av,    g_a);
    cudaGetSymbolAddress((void**)&bvv,   g_b);
    cudaGetSymbolAddress((void**)&cs,    g_c);
    cudaGetSymbolAddress((void**)&zs,    g_zero);

    float* Yout = (float*)d_out;
    const long YSIZE = (long)BATCH * SQ * DM;
    const long ASIZE = (long)BATCH * NH * SQ * SK;
    float* out_att = ((long)out_size >= YSIZE + ASIZE) ? (Yout + YSIZE) : nullptr;
    const float inv_scale = 1.0f / sqrtf((float)DM);

    cudaFuncSetAttribute(gemm_h<0,0>, cudaFuncAttributeMaxDynamicSharedMemorySize, GEMM_SMEM);
    cudaFuncSetAttribute(gemm_h<0,1>, cudaFuncAttributeMaxDynamicSharedMemorySize, GEMM_SMEM);
    cudaFuncSetAttribute(gemm_h<1,0>, cudaFuncAttributeMaxDynamicSharedMemorySize, GEMM_SMEM);
    cudaFuncSetAttribute(gemm_h<2,1>, cudaFuncAttributeMaxDynamicSharedMemorySize, GEMM_SMEM);

    // lazily-created side streams + events
    static cudaStream_t sA = nullptr, sB = nullptr;
    static cudaEvent_t  e0 = nullptr, eVd = nullptr, eKc = nullptr,
                        eK0 = nullptr, eK1 = nullptr, eV0 = nullptr, eV1 = nullptr,
                        eS0 = nullptr, eS1 = nullptr, eSm0 = nullptr, eSm1 = nullptr,
                        eB = nullptr;
    if (!sA) {
        cudaStreamCreateWithFlags(&sA, cudaStreamNonBlocking);
        cudaStreamCreateWithFlags(&sB, cudaStreamNonBlocking);
        cudaEventCreateWithFlags(&e0,  cudaEventDisableTiming);
        cudaEventCreateWithFlags(&eVd, cudaEventDisableTiming);
        cudaEventCreateWithFlags(&eKc, cudaEventDisableTiming);
        cudaEventCreateWithFlags(&eK0, cudaEventDisableTiming);
        cudaEventCreateWithFlags(&eK1, cudaEventDisableTiming);
        cudaEventCreateWithFlags(&eV0, cudaEventDisableTiming);
        cudaEventCreateWithFlags(&eV1, cudaEventDisableTiming);
        cudaEventCreateWithFlags(&eS0, cudaEventDisableTiming);
        cudaEventCreateWithFlags(&eS1, cudaEventDisableTiming);
        cudaEventCreateWithFlags(&eSm0, cudaEventDisableTiming);
        cudaEventCreateWithFlags(&eSm1, cudaEventDisableTiming);
        cudaEventCreateWithFlags(&eB,  cudaEventDisableTiming);
    }
    const bool ok = (sA && sB && e0 && eVd && eKc && eK0 && eK1 && eV0 && eV1 &&
                     eS0 && eS1 && eSm0 && eSm1 && eB);
    cudaStream_t wA = ok ? sA : (cudaStream_t)0;
    cudaStream_t wB = ok ? sB : (cudaStream_t)0;

    const int NBIG = (BATCH * SQ * DM) / 1024;
    const int NSML = (DM * DM) / 1024;

    // per-half offsets
    const long oQK  = (long)HALF * SQ * DM;      // Qh/Kh/Km (half, elements)
    const long oATT = (long)HALF * SQ * SK;      // att / att_h
    const long oVW  = (long)HALF * DM * SK;      // VWt
    const long oOA  = (long)HALF * NH * SQ * SK; // out_att replicas
    const long oY   = (long)HALF * SQ * DM;      // Y

    if (ok) { cudaEventRecord(e0, 0); cudaStreamWaitEvent(wA, e0, 0); cudaStreamWaitEvent(wB, e0, 0); }

    // ---- streamB: tiny rank-1 precomputes ----
    dot512<<<1, 256, 0, wB>>>(bq, bk, cs);
    vecdot512<<<DM, 128, 0, wB>>>(Wq, bk, wqbk);
    vecdot512<<<DM, 128, 0, wB>>>(Wk, bq, wkbq);
    if (ok) cudaEventRecord(eVd, wB);

    // ---- stream0: K convert first (gates Km), then Q convert + rowdots ----
    f32_to_f16<<<NBIG, 256>>>(K, Kh);
    if (ok) cudaEventRecord(eKc, 0);
    f32_to_f16<<<NBIG, 256>>>(Q, Qh);
    if (ok) cudaStreamWaitEvent(0, eVd, 0);
    rowdot<<<BATCH * SQ, 128>>>(Q, wqbk, cs, av, inv_scale);
    rowdot<<<BATCH * SK, 128>>>(K, wkbq, zs, bvv, inv_scale);

    // ---- streamA: M~ then Km halves then V path ----
    f32_to_f16<<<NSML, 256, 0, wA>>>(Wq, Wqh);
    f32_to_f16<<<NSML, 256, 0, wA>>>(Wk, Wkh);
    gemm_h<0,1><<<dim3(DM / BN, DM / BM, 4), 256, GEMM_SMEM, wA>>>(
        Wqh, Wkh, wcP, 128, 128, 128, (long)DM * DM,
        nullptr, nullptr, 0.f, 0, 0, DM, DM, nullptr, nullptr);
    reduce4<<<DM * DM / 1024, 256, 0, wA>>>(wcP, Mh);
    if (ok) cudaStreamWaitEvent(wA, eKc, 0);
    gemm_h<0,1><<<dim3(DM / BN, (HALF * SK) / BM, 1), 256, GEMM_SMEM, wA>>>(
        Kh, Mh, Km, DM, 0, 0, 0, nullptr, nullptr, 0.f, 0, 0, DM, DM, nullptr, nullptr);
    if (ok) cudaEventRecord(eK0, wA);
    gemm_h<0,1><<<dim3(DM / BN, (HALF * SK) / BM, 1), 256, GEMM_SMEM, wA>>>(
        Kh + oQK, Mh, Km + oQK, DM, 0, 0, 0, nullptr, nullptr, 0.f, 0, 0, DM, DM,
        nullptr, nullptr);
    if (ok) cudaEventRecord(eK1, wA);
    // V / output-projection path
    f32_to_f16<<<NBIG, 256, 0, wA>>>(V, Vh);
    f32_to_f16<<<NSML, 256, 0, wA>>>(Wv, Wvh);
    wl_sumT_tiled<<<dim3(16, 16), dim3(32, 8), 0, wA>>>(Wl, wleT);
    bc_kernel<<<DM, 256, 0, wA>>>(bl, bv, wleT, bc);
    gemm_h<2,1><<<dim3(DM / BN, DM / BM, 4), 256, GEMM_SMEM, wA>>>(
        Wvh, wleT, wcP, 128, 128, 128, (long)DM * DM,
        nullptr, nullptr, 0.f, DM, 0, DM, DM, nullptr, nullptr);
    reduce4<<<DM * DM / 1024, 256, 0, wA>>>(wcP, wcT);
    gemm_h<2,1><<<dim3(DM / BN, (HALF * SK) / BM, 1), 256, GEMM_SMEM, wA>>>(
        Vh, wcT, VWt, DM, 0, 0, 0, nullptr, nullptr, 0.f, SK, (long)DM * SK, DM, DM,
        nullptr, nullptr);
    if (ok) cudaEventRecord(eV0, wA);
    gemm_h<2,1><<<dim3(DM / BN, (HALF * SK) / BM, 1), 256, GEMM_SMEM, wA>>>(
        Vh + oQK, wcT, VWt + oVW, DM, 0, 0, 0, nullptr, nullptr, 0.f, SK,
        (long)DM * SK, DM, DM, nullptr, nullptr);
    if (ok) cudaEventRecord(eV1, wA);

    // ---- stream0: scores halves ----
    if (ok) cudaStreamWaitEvent(0, eK0, 0);
    gemm_h<1,0><<<dim3(SK / BN, SQ / BM, HALF), 256, GEMM_SMEM>>>(
        Qh, Km, att, DM, (long)SQ * DM, (long)SK * DM, (long)SQ * SK,
        nullptr, mask, inv_scale, 0, 0, DM, DM, av, bvv);
    if (ok) cudaEventRecord(eS0, 0);
    if (ok) cudaStreamWaitEvent(0, eK1, 0);
    gemm_h<1,0><<<dim3(SK / BN, SQ / BM, HALF), 256, GEMM_SMEM>>>(
        Qh + oQK, Km + oQK, att + oATT, DM, (long)SQ * DM, (long)SK * DM, (long)SQ * SK,
        nullptr, mask + HALF * SK, inv_scale, 0, 0, DM, DM, av + HALF * SQ,
        bvv + HALF * SK);
    if (ok) cudaEventRecord(eS1, 0);

    // ---- streamB: softmax halves + replicate ----
    if (ok) cudaStreamWaitEvent(wB, eS0, 0);
    softmax_head0<<<dim3(SQ, HALF), 256, 0, wB>>>(att, att_h, out_att);
    if (ok) cudaEventRecord(eSm0, wB);
    if (ok) cudaStreamWaitEvent(wB, eS1, 0);
    softmax_head0<<<dim3(SQ, HALF), 256, 0, wB>>>(
        att + oATT, att_h + oATT, out_att ? out_att + oOA : nullptr);
    if (ok) cudaEventRecord(eSm1, wB);
    if (out_att) {
        replicate7<<<dim3(SQ, HALF), 256, 0, wB>>>(out_att);
        replicate7<<<dim3(SQ, HALF), 256, 0, wB>>>(out_att + oOA);
    }
    if (ok) cudaEventRecord(eB, wB);

    // ---- stream0: final halves ----
    if (ok) { cudaStreamWaitEvent(0, eSm0, 0); cudaStreamWaitEvent(0, eV0, 0); }
    gemm_h<0,0><<<dim3(DM / BN, SQ / BM, HALF), 256, GEMM_SMEM>>>(
        att_h, VWt, Yout, SK, (long)SQ * SK, (long)DM * SK, (long)SQ * DM,
        bc, nullptr, 0.f, 0, 0, SK, SK, nullptr, nullptr);
    if (ok) { cudaStreamWaitEvent(0, eSm1, 0); cudaStreamWaitEvent(0, eV1, 0); }
    gemm_h<0,0><<<dim3(DM / BN, SQ / BM, HALF), 256, GEMM_SMEM>>>(
        att_h + oATT, VWt + oVW, Yout + oY, SK, (long)SQ * SK, (long)DM * SK,
        (long)SQ * DM, bc, nullptr, 0.f, 0, 0, SK, SK, nullptr, nullptr);

    // ---- join replicate leg ----
    if (ok) cudaStreamWaitEvent(0, eB, 0);
}

// round 13
// speedup vs baseline: 1.1752x; 1.1752x over previous
#include <cuda_runtime.h>
#include <cuda_fp16.h>
#include <math.h>
#include <stdint.h>

// Problem constants
#define BATCH 8
#define SQ    1024
#define SK    1024
#define DM    512
#define NH    8

// ---------------- device scratch ----------------------------------------------
__device__ __half g_Qh[BATCH * SQ * DM];
__device__ __half g_Kh[BATCH * SK * DM];
__device__ __half g_Vh[BATCH * SK * DM];
__device__ __half g_Wqh[DM * DM];
__device__ __half g_Wkh[DM * DM];
__device__ __half g_Wvh[DM * DM];
__device__ __half g_M[DM * DM];              // M~ = Wq @ Wk^T (fp16)
__device__ __half g_Km[BATCH * SK * DM];     // K @ M~^T per batch
__device__ __half g_VWt[BATCH * DM * SK];    // (V @ Wc)^T per batch: [b][d][sk]
__device__ float  g_att[BATCH * SQ * SK];    // fp32 scores
__device__ __half g_att_h[BATCH * SQ * SK];  // fp16 probs (final GEMM A)
__device__ __half g_WleT[DM * DM];
__device__ __half g_WcT[DM * DM];
__device__ __half g_WcP[4 * DM * DM];        // shared split-K partials (M~ then WcT)
__device__ float  g_bc[DM];
__device__ float  g_wqbk[DM];
__device__ float  g_wkbq[DM];
__device__ float  g_a[BATCH * SQ];           // row bias for scores
__device__ float  g_b[BATCH * SK];           // col bias for scores
__device__ float  g_c[1];
__device__ float  g_zero = 0.f;              // never written

// ---------------- PTX helpers --------------------------------------------------
__device__ __forceinline__ uint32_t smem_u32(const void* p) {
    uint32_t a;
    asm("{ .reg .u64 t; cvta.to.shared.u64 t, %1; cvt.u32.u64 %0, t; }" : "=r"(a) : "l"(p));
    return a;
}

#define CP_ASYNC16(dst, src) \
    asm volatile("cp.async.cg.shared.global [%0], [%1], 16;" :: "r"(dst), "l"(src) : "memory")
#define CP_COMMIT() asm volatile("cp.async.commit_group;" ::: "memory")
#define CP_WAIT2()  asm volatile("cp.async.wait_group 2;" ::: "memory")
#define CP_WAIT1()  asm volatile("cp.async.wait_group 1;" ::: "memory")
#define CP_WAIT0()  asm volatile("cp.async.wait_group 0;" ::: "memory")

#define LDSM4(r0, r1, r2, r3, addr) \
    asm volatile("ldmatrix.sync.aligned.m8n8.x4.shared.b16 {%0,%1,%2,%3}, [%4];" \
        : "=r"(r0), "=r"(r1), "=r"(r2), "=r"(r3) : "r"(addr))

__device__ __forceinline__ void mma_f16(float* c, const uint32_t* a, const uint32_t* b) {
    asm volatile(
        "mma.sync.aligned.m16n8k16.row.col.f32.f16.f16.f32 "
        "{%0,%1,%2,%3}, {%4,%5,%6,%7}, {%8,%9}, {%0,%1,%2,%3};"
        : "+f"(c[0]), "+f"(c[1]), "+f"(c[2]), "+f"(c[3])
        : "r"(a[0]), "r"(a[1]), "r"(a[2]), "r"(a[3]), "r"(b[0]), "r"(b[1]));
}

// ================================================================================
// fp16 mma.sync GEMM: C[M,N] = A[M,K] @ B[N,K]^T   (fp32 accumulate)
// Block tile 256x128x32, 8 warps (4x2), warp tile 64x64, 3-stage cp.async ring,
// ldmatrix.x4 fragment loads (conflict-free with LDH=40 stride).
// MODE 0: C += bias[n]; output fp16 if OUT_HALF else fp32
// MODE 1: C = C*scale + rowb[bz*SQ+m] + colb[bz*SK+n] + mask[bz][n]*-1e9 (fp32 out)
// MODE 2: transposed fp16 store: out[b2*foldT + n*ldT + mloc]
// grid (N/128, M/256, batches-or-ksplits), 256 threads
// ================================================================================
#define BM 256
#define BN 128
#define BK 32
#define LDH 40
#define A_TILE_H (BM * LDH)                      // 10240
#define B_TILE_H (BN * LDH)                      // 5120
#define STAGE_H  (A_TILE_H + B_TILE_H)           // 15360
#define NSTAGE 3
#define GEMM_SMEM (NSTAGE * STAGE_H * 2)         // 92160 B

template <int MODE, int OUT_HALF>
__global__ void __launch_bounds__(256, 1) gemm_h(
    const __half* __restrict__ A, const __half* __restrict__ B, void* __restrict__ Cv,
    int Kdim, long sA, long sB, long sC,
    const float* __restrict__ bias, const int* __restrict__ mask, float scale,
    int ldT, long foldT, int lda, int ldb,
    const float* __restrict__ rowb, const float* __restrict__ colb)
{
    extern __shared__ __half smem[];
    const uint32_t smb = smem_u32(smem);

    const int tid = threadIdx.x;
    const int lane = tid & 31, wid = tid >> 5;
    const int g = lane >> 2, t = lane & 3;
    const int wm = wid >> 1, wn = wid & 1;       // 4 x 2 warps, warp tile 64x64
    const int m0 = blockIdx.y * BM, n0 = blockIdx.x * BN, bz = blockIdx.z;

    const __half* Ag = A + (long)bz * sA;
    const __half* Bg = B + (long)bz * sB;

    float acc[4][8][4];
#pragma unroll
    for (int i = 0; i < 4; i++)
#pragma unroll
        for (int j = 0; j < 8; j++)
#pragma unroll
            for (int r = 0; r < 4; r++) acc[i][j][r] = 0.f;

    const int NC = Kdim / BK;
    const int lrow = tid >> 2, lchunk = (tid & 3) * 8;   // cp.async slots

    const int lj = lane >> 3, lr8 = lane & 7;
    uint32_t aoff[4], boff[4];
#pragma unroll
    for (int mt = 0; mt < 4; mt++)
        aoff[mt] = (uint32_t)(((wm * 64 + mt * 16 + lr8 + 8 * (lj & 1)) * LDH
                               + 8 * (lj >> 1)) * 2);
#pragma unroll
    for (int np = 0; np < 4; np++)
        boff[np] = (uint32_t)((A_TILE_H + (wn * 64 + np * 16 + lr8 + 8 * (lj >> 1)) * LDH
                               + 8 * (lj & 1)) * 2);

    auto issue = [&](int c, int s) {
        const long k0 = (long)c * BK;
        const uint32_t abase = smb + (uint32_t)(s * STAGE_H * 2);
        const uint32_t bbase = abase + (uint32_t)(A_TILE_H * 2);
#pragma unroll
        for (int j = 0; j < 4; j++) {
            int row = lrow + 64 * j;
            CP_ASYNC16(abase + (uint32_t)((row * LDH + lchunk) * 2),
                       Ag + (long)(m0 + row) * lda + k0 + lchunk);
        }
#pragma unroll
        for (int j = 0; j < 2; j++) {
            int row = lrow + 64 * j;
            CP_ASYNC16(bbase + (uint32_t)((row * LDH + lchunk) * 2),
                       Bg + (long)(n0 + row) * ldb + k0 + lchunk);
        }
        CP_COMMIT();
    };

    issue(0, 0);
    if (NC > 1) issue(1, 1);

    for (int c = 0; c < NC; c++) {
        const int buf = c % NSTAGE;
        if (c + 2 < NC) { issue(c + 2, (c + 2) % NSTAGE); CP_WAIT2(); }
        else if (c + 1 < NC) { CP_WAIT1(); }
        else { CP_WAIT0(); }
        __syncthreads();

        const uint32_t sbase = smb + (uint32_t)(buf * STAGE_H * 2);

#pragma unroll
        for (int kk = 0; kk < 2; kk++) {
            const uint32_t kboff = (uint32_t)(kk * 16 * 2);
            uint32_t af[4][4], bf[8][2];
#pragma unroll
            for (int mt = 0; mt < 4; mt++)
                LDSM4(af[mt][0], af[mt][1], af[mt][2], af[mt][3],
                      sbase + aoff[mt] + kboff);
#pragma unroll
            for (int np = 0; np < 4; np++)
                LDSM4(bf[2 * np][0], bf[2 * np][1], bf[2 * np + 1][0], bf[2 * np + 1][1],
                      sbase + boff[np] + kboff);
#pragma unroll
            for (int mt = 0; mt < 4; mt++)
#pragma unroll
                for (int nt = 0; nt < 8; nt++)
                    mma_f16(acc[mt][nt], af[mt], bf[nt]);
        }
        __syncthreads();
    }

    // ---- epilogue ----
    if (MODE == 2) {
        __half* Cz = (__half*)Cv + (long)bz * sC;
        __half* stage = smem;                    // [128][264] halves (n x m)
#pragma unroll
        for (int mt = 0; mt < 4; mt++) {
            const int r0 = wm * 64 + mt * 16 + g;
#pragma unroll
            for (int nt = 0; nt < 8; nt++) {
                const int c0 = wn * 64 + nt * 8 + t * 2;
                stage[(c0    ) * 264 + r0    ] = __float2half_rn(acc[mt][nt][0]);
                stage[(c0 + 1) * 264 + r0    ] = __float2half_rn(acc[mt][nt][1]);
                stage[(c0    ) * 264 + r0 + 8] = __float2half_rn(acc[mt][nt][2]);
                stage[(c0 + 1) * 264 + r0 + 8] = __float2half_rn(acc[mt][nt][3]);
            }
        }
        __syncthreads();
        const int b2 = m0 >> 10, mq = tid & 63, rq = tid >> 6;
        const int mloc = (m0 & 1023) + mq * 4;
#pragma unroll
        for (int it = 0; it < 32; it++) {
            const int nr = rq + it * 4;
            uint2 v = *(const uint2*)&stage[nr * 264 + mq * 4];
            *(uint2*)&Cz[(long)b2 * foldT + (long)(n0 + nr) * ldT + mloc] = v;
        }
        return;
    }

    const int ldc = gridDim.x * BN;
#pragma unroll
    for (int mt = 0; mt < 4; mt++) {
        const int r0 = m0 + wm * 64 + mt * 16 + g;
#pragma unroll
        for (int nt = 0; nt < 8; nt++) {
            const int c0 = n0 + wn * 64 + nt * 8 + t * 2;
            float2 v0 = { acc[mt][nt][0], acc[mt][nt][1] };
            float2 v1 = { acc[mt][nt][2], acc[mt][nt][3] };
            if (MODE == 0) {
                if (bias) {
                    v0.x += bias[c0]; v0.y += bias[c0 + 1];
                    v1.x += bias[c0]; v1.y += bias[c0 + 1];
                }
                if (OUT_HALF) {
                    __half* Cg = (__half*)Cv + (long)bz * sC;
                    *(__half2*)&Cg[(long)r0 * ldc + c0]       = __floats2half2_rn(v0.x, v0.y);
                    *(__half2*)&Cg[(long)(r0 + 8) * ldc + c0] = __floats2half2_rn(v1.x, v1.y);
                    continue;
                }
            } else { // MODE 1: scale + row/col rank-1 bias + mask
                const int* mk = mask + (long)bz * SK;
                float p0 = mk[c0] ? -1e9f : 0.f, p1 = mk[c0 + 1] ? -1e9f : 0.f;
                float ra  = rowb[(long)bz * SQ + r0];
                float ra8 = rowb[(long)bz * SQ + r0 + 8];
                float cb0 = colb[(long)bz * SK + c0];
                float cb1 = colb[(long)bz * SK + c0 + 1];
                v0.x = v0.x * scale + ra  + cb0 + p0; v0.y = v0.y * scale + ra  + cb1 + p1;
                v1.x = v1.x * scale + ra8 + cb0 + p0; v1.y = v1.y * scale + ra8 + cb1 + p1;
            }
            float* Cg = (float*)Cv + (long)bz * sC;
            *(float2*)&Cg[(long)r0 * ldc + c0]       = v0;
            *(float2*)&Cg[(long)(r0 + 8) * ldc + c0] = v1;
        }
    }
}

// ================================================================================
// helper kernels
// ================================================================================
__global__ void f32_to_f16(const float* __restrict__ in, __half* __restrict__ out) {
    long i = ((long)blockIdx.x * 256 + threadIdx.x) * 4;
    float4 v = *(const float4*)&in[i];
    __half2 h0 = __floats2half2_rn(v.x, v.y);
    __half2 h1 = __floats2half2_rn(v.z, v.w);
    uint2 p = { *(uint32_t*)&h0, *(uint32_t*)&h1 };
    *(uint2*)&out[i] = p;
}

__global__ void wl_sumT_tiled(const float* __restrict__ Wl, __half* __restrict__ WleT) {
    __shared__ float t[32][33];
    int bx = blockIdx.x * 32, by = blockIdx.y * 32;
    for (int i = threadIdx.y; i < 32; i += 8) {
        float s = 0.f;
#pragma unroll
        for (int h = 0; h < NH; h++)
            s += Wl[((long)(h * DM) + by + i) * DM + bx + threadIdx.x];
        t[i][threadIdx.x] = s;
    }
    __syncthreads();
    for (int i = threadIdx.y; i < 32; i += 8)
        WleT[(bx + i) * DM + by + threadIdx.x] = __float2half_rn(t[threadIdx.x][i]);
}

__global__ void bc_kernel(const float* __restrict__ bl, const float* __restrict__ bv,
                          const __half* __restrict__ WleT, float* __restrict__ bc) {
    const int n = blockIdx.x, t = threadIdx.x;
    __shared__ float red[256];
    float s = 0.f;
    for (int k = t; k < DM; k += 256) s += bv[k] * __half2float(WleT[n * DM + k]);
    red[t] = s;
    __syncthreads();
#pragma unroll
    for (int o = 128; o >= 32; o >>= 1) {
        if (t < o) red[t] += red[t + o];
        __syncthreads();
    }
    if (t < 32) {
        float v = red[t];
#pragma unroll
        for (int o = 16; o > 0; o >>= 1)
            v += __shfl_down_sync(0xffffffffu, v, o);
        if (t == 0) bc[n] = bl[n] + v;
    }
}

__global__ void dot512(const float* __restrict__ a, const float* __restrict__ b,
                       float* __restrict__ out) {
    const int t = threadIdx.x;
    __shared__ float red[256];
    float s = 0.f;
    for (int k = t; k < DM; k += 256) s += a[k] * b[k];
    red[t] = s;
    __syncthreads();
#pragma unroll
    for (int o = 128; o >= 32; o >>= 1) {
        if (t < o) red[t] += red[t + o];
        __syncthreads();
    }
    if (t < 32) {
        float v = red[t];
#pragma unroll
        for (int o = 16; o > 0; o >>= 1)
            v += __shfl_down_sync(0xffffffffu, v, o);
        if (t == 0) out[0] = v;
    }
}

__global__ void vecdot512(const float* __restrict__ W, const float* __restrict__ v,
                          float* __restrict__ out) {
    const int f = blockIdx.x, t = threadIdx.x;
    __shared__ float red[128];
    float s = 0.f;
    for (int k = t; k < DM; k += 128) s += W[(long)f * DM + k] * v[k];
    red[t] = s;
    __syncthreads();
#pragma unroll
    for (int o = 64; o >= 32; o >>= 1) {
        if (t < o) red[t] += red[t + o];
        __syncthreads();
    }
    if (t < 32) {
        float x = red[t];
#pragma unroll
        for (int o = 16; o > 0; o >>= 1)
            x += __shfl_down_sync(0xffffffffu, x, o);
        if (t == 0) out[f] = x;
    }
}

__global__ void rowdot(const float* __restrict__ X, const float* __restrict__ vec,
                       const float* __restrict__ cadd, float* __restrict__ out,
                       float scale) {
    const int r = blockIdx.x, t = threadIdx.x;
    __shared__ float red[128];
    float s = 0.f;
    for (int k = t; k < DM; k += 128) s += X[(long)r * DM + k] * vec[k];
    red[t] = s;
    __syncthreads();
#pragma unroll
    for (int o = 64; o >= 32; o >>= 1) {
        if (t < o) red[t] += red[t + o];
        __syncthreads();
    }
    if (t < 32) {
        float x = red[t];
#pragma unroll
        for (int o = 16; o > 0; o >>= 1)
            x += __shfl_down_sync(0xffffffffu, x, o);
        if (t == 0) out[r] = (x + cadd[0]) * scale;
    }
}

__global__ void reduce4(const __half* __restrict__ p, __half* __restrict__ o) {
    long i = ((long)blockIdx.x * 256 + threadIdx.x) * 4;
    float s[4];
#pragma unroll
    for (int j = 0; j < 4; j++) s[j] = 0.f;
#pragma unroll
    for (int part = 0; part < 4; part++) {
        uint2 v = *(const uint2*)&p[(long)part * DM * DM + i];
        __half2 h0 = *(__half2*)&v.x, h1 = *(__half2*)&v.y;
        s[0] += __low2float(h0);  s[1] += __high2float(h0);
        s[2] += __low2float(h1);  s[3] += __high2float(h1);
    }
    __half2 r0 = __floats2half2_rn(s[0], s[1]);
    __half2 r1 = __floats2half2_rn(s[2], s[3]);
    uint2 r = { *(uint32_t*)&r0, *(uint32_t*)&r1 };
    *(uint2*)&o[i] = r;
}

// fused softmax; writes fp16 probs to att_h + fp32 replica 0
__global__ void softmax_head0(const float* __restrict__ att, __half* __restrict__ att_h,
                              float* __restrict__ out_att) {
    const int q = blockIdx.x, b = blockIdx.y, t = threadIdx.x;
    const float* row = att + ((long)(b * SQ + q)) * SK;
    float4 v = ((const float4*)row)[t];

    __shared__ float red[256];
    float m = fmaxf(fmaxf(v.x, v.y), fmaxf(v.z, v.w));
    red[t] = m;
    __syncthreads();
#pragma unroll
    for (int s = 128; s > 0; s >>= 1) {
        if (t < s) red[t] = fmaxf(red[t], red[t + s]);
        __syncthreads();
    }
    m = red[0];
    __syncthreads();

    float4 e;
    e.x = expf(v.x - m); e.y = expf(v.y - m);
    e.z = expf(v.z - m); e.w = expf(v.w - m);
    red[t] = e.x + e.y + e.z + e.w;
    __syncthreads();
#pragma unroll
    for (int s = 128; s > 0; s >>= 1) {
        if (t < s) red[t] += red[t + s];
        __syncthreads();
    }
    float inv = 1.0f / red[0];
    e.x *= inv; e.y *= inv; e.z *= inv; e.w *= inv;

    __half2 h0 = __floats2half2_rn(e.x, e.y);
    __half2 h1 = __floats2half2_rn(e.z, e.w);
    uint2 ph = { *(uint32_t*)&h0, *(uint32_t*)&h1 };
    ((uint2*)(att_h + ((long)(b * SQ + q)) * SK))[t] = ph;

    if (out_att)
        ((float4*)(out_att + (((long)(b * NH) * SQ) + q) * SK))[t] = e;
}

// copy replica 0 -> replicas 1..7 (pure HBM fanout; overlaps final GEMM)
__global__ void replicate7(float* __restrict__ out_att) {
    const int q = blockIdx.x, b = blockIdx.y, t = threadIdx.x;
    const float4* src = (const float4*)(out_att + (((long)(b * NH) * SQ) + q) * SK);
    float4 v = src[t];
#pragma unroll
    for (int h = 1; h < NH; h++)
        ((float4*)(out_att + (((long)(b * NH + h) * SQ) + q) * SK))[t] = v;
}

// ================================================================================
// launch — R11 structure; convK early on stream0, rank-1 helpers on streamB
// ================================================================================
extern "C" void kernel_launch(void* const* d_in, const int* in_sizes, int n_in,
                              void* d_out, int out_size) {
    const float* Q    = (const float*)d_in[0];
    const float* K    = (const float*)d_in[1];
    const float* V    = (const float*)d_in[2];
    const int*   mask = (const int*)  d_in[3];
    const float* Wq   = (const float*)d_in[4];
    const float* bq   = (const float*)d_in[5];
    const float* Wk   = (const float*)d_in[6];
    const float* bk   = (const float*)d_in[7];
    const float* Wv   = (const float*)d_in[8];
    const float* bv   = (const float*)d_in[9];
    const float* Wl   = (const float*)d_in[10];
    const float* bl   = (const float*)d_in[11];

    __half *Qh, *Kh, *Vh, *Wqh, *Wkh, *Wvh, *Mh, *Km, *VWt, *att_h, *wleT, *wcT, *wcP;
    float *att, *bc, *wqbk, *wkbq, *av, *bvv, *cs, *zs;
    cudaGetSymbolAddress((void**)&Qh,    g_Qh);
    cudaGetSymbolAddress((void**)&Kh,    g_Kh);
    cudaGetSymbolAddress((void**)&Vh,    g_Vh);
    cudaGetSymbolAddress((void**)&Wqh,   g_Wqh);
    cudaGetSymbolAddress((void**)&Wkh,   g_Wkh);
    cudaGetSymbolAddress((void**)&Wvh,   g_Wvh);
    cudaGetSymbolAddress((void**)&Mh,    g_M);
    cudaGetSymbolAddress((void**)&Km,    g_Km);
    cudaGetSymbolAddress((void**)&VWt,   g_VWt);
    cudaGetSymbolAddress((void**)&att,   g_att);
    cudaGetSymbolAddress((void**)&att_h, g_att_h);
    cudaGetSymbolAddress((void**)&wleT,  g_WleT);
    cudaGetSymbolAddress((void**)&wcT,   g_WcT);
    cudaGetSymbolAddress((void**)&wcP,   g_WcP);
    cudaGetSymbolAddress((void**)&bc,    g_bc);
    cudaGetSymbolAddress((void**)&wqbk,  g_wqbk);
    cudaGetSymbolAddress((void**)&wkbq,  g_wkbq);
    cudaGetSymbolAddress((void**)&av,    g_a);
    cudaGetSymbolAddress((void**)&bvv,   g_b);
    cudaGetSymbolAddress((void**)&cs,    g_c);
    cudaGetSymbolAddress((void**)&zs,    g_zero);

    float* Yout = (float*)d_out;
    const long YSIZE = (long)BATCH * SQ * DM;
    const long ASIZE = (long)BATCH * NH * SQ * SK;
    float* out_att = ((long)out_size >= YSIZE + ASIZE) ? (Yout + YSIZE) : nullptr;
    const float inv_scale = 1.0f / sqrtf((float)DM);

    cudaFuncSetAttribute(gemm_h<0,0>, cudaFuncAttributeMaxDynamicSharedMemorySize, GEMM_SMEM);
    cudaFuncSetAttribute(gemm_h<0,1>, cudaFuncAttributeMaxDynamicSharedMemorySize, GEMM_SMEM);
    cudaFuncSetAttribute(gemm_h<1,0>, cudaFuncAttributeMaxDynamicSharedMemorySize, GEMM_SMEM);
    cudaFuncSetAttribute(gemm_h<2,1>, cudaFuncAttributeMaxDynamicSharedMemorySize, GEMM_SMEM);

    // lazily-created side streams + events (capture-safe; no device allocs)
    static cudaStream_t sA = nullptr, sB = nullptr;
    static cudaEvent_t  e0 = nullptr, eKc = nullptr, eR = nullptr, eK = nullptr,
                        eA = nullptr, eS = nullptr, eB = nullptr;
    if (!sA) {
        cudaStreamCreateWithFlags(&sA, cudaStreamNonBlocking);
        cudaStreamCreateWithFlags(&sB, cudaStreamNonBlocking);
        cudaEventCreateWithFlags(&e0,  cudaEventDisableTiming);
        cudaEventCreateWithFlags(&eKc, cudaEventDisableTiming);
        cudaEventCreateWithFlags(&eR,  cudaEventDisableTiming);
        cudaEventCreateWithFlags(&eK,  cudaEventDisableTiming);
        cudaEventCreateWithFlags(&eA,  cudaEventDisableTiming);
        cudaEventCreateWithFlags(&eS,  cudaEventDisableTiming);
        cudaEventCreateWithFlags(&eB,  cudaEventDisableTiming);
    }
    const bool ok = (sA && sB && e0 && eKc && eR && eK && eA && eS && eB);
    cudaStream_t wA = ok ? sA : (cudaStream_t)0;   // weight/K leg
    cudaStream_t wB = ok ? sB : (cudaStream_t)0;   // helpers / replicate leg

    const int NBIG = (BATCH * SQ * DM) / 1024;
    const int NSML = (DM * DM) / 1024;

    if (ok) {
        cudaEventRecord(e0, 0);
        cudaStreamWaitEvent(wA, e0, 0);
        cudaStreamWaitEvent(wB, e0, 0);
    }

    // ---- stream0: K convert first (gates Km), then Q convert ----
    f32_to_f16<<<NBIG, 256>>>(K, Kh);
    if (ok) cudaEventRecord(eKc, 0);
    f32_to_f16<<<NBIG, 256>>>(Q, Qh);

    // ---- streamB: rank-1 precomputes (feed scores epilogue only) ----
    dot512<<<1, 256, 0, wB>>>(bq, bk, cs);
    vecdot512<<<DM, 128, 0, wB>>>(Wq, bk, wqbk);
    vecdot512<<<DM, 128, 0, wB>>>(Wk, bq, wkbq);
    rowdot<<<BATCH * SQ, 128, 0, wB>>>(Q, wqbk, cs, av, inv_scale);
    rowdot<<<BATCH * SK, 128, 0, wB>>>(K, wkbq, zs, bvv, inv_scale);
    if (ok) cudaEventRecord(eR, wB);

    // ---- streamA: M~ then Km (full batch), then V/output path ----
    f32_to_f16<<<NSML, 256, 0, wA>>>(Wq, Wqh);
    f32_to_f16<<<NSML, 256, 0, wA>>>(Wk, Wkh);
    gemm_h<0,1><<<dim3(DM / BN, DM / BM, 4), 256, GEMM_SMEM, wA>>>(
        Wqh, Wkh, wcP, 128, 128, 128, (long)DM * DM,
        nullptr, nullptr, 0.f, 0, 0, DM, DM, nullptr, nullptr);
    reduce4<<<DM * DM / 1024, 256, 0, wA>>>(wcP, Mh);
    if (ok) cudaStreamWaitEvent(wA, eKc, 0);
    gemm_h<0,1><<<dim3(DM / BN, (BATCH * SK) / BM, 1), 256, GEMM_SMEM, wA>>>(
        Kh, Mh, Km, DM, 0, 0, 0, nullptr, nullptr, 0.f, 0, 0, DM, DM, nullptr, nullptr);
    if (ok) cudaEventRecord(eK, wA);
    f32_to_f16<<<NBIG, 256, 0, wA>>>(V, Vh);
    f32_to_f16<<<NSML, 256, 0, wA>>>(Wv, Wvh);
    wl_sumT_tiled<<<dim3(16, 16), dim3(32, 8), 0, wA>>>(Wl, wleT);
    bc_kernel<<<DM, 256, 0, wA>>>(bl, bv, wleT, bc);
    gemm_h<2,1><<<dim3(DM / BN, DM / BM, 4), 256, GEMM_SMEM, wA>>>(
        Wvh, wleT, wcP, 128, 128, 128, (long)DM * DM,
        nullptr, nullptr, 0.f, DM, 0, DM, DM, nullptr, nullptr);
    reduce4<<<DM * DM / 1024, 256, 0, wA>>>(wcP, wcT);
    gemm_h<2,1><<<dim3(DM / BN, (BATCH * SK) / BM, 1), 256, GEMM_SMEM, wA>>>(
        Vh, wcT, VWt, DM, 0, 0, 0, nullptr, nullptr, 0.f, SK, (long)DM * SK, DM, DM,
        nullptr, nullptr);
    if (ok) cudaEventRecord(eA, wA);

    // ---- stream0: scores = Qh @ Km^T * s + a + b + mask ----
    if (ok) { cudaStreamWaitEvent(0, eK, 0); cudaStreamWaitEvent(0, eR, 0); }
    gemm_h<1,0><<<dim3(SK / BN, SQ / BM, BATCH), 256, GEMM_SMEM>>>(
        Qh, Km, att, DM, (long)SQ * DM, (long)SK * DM, (long)SQ * SK,
        nullptr, mask, inv_scale, 0, 0, DM, DM, av, bvv);
    softmax_head0<<<dim3(SQ, BATCH), 256>>>(att, att_h, out_att);

    // ---- fork replicate leg ----
    if (out_att) {
        if (ok) {
            cudaEventRecord(eS, 0);
            cudaStreamWaitEvent(wB, eS, 0);
        }
        replicate7<<<dim3(SQ, BATCH), 256, 0, wB>>>(out_att);
        if (ok) cudaEventRecord(eB, wB);
    }

    // ---- join leg A; final GEMM ----
    if (ok) cudaStreamWaitEvent(0, eA, 0);
    gemm_h<0,0><<<dim3(DM / BN, SQ / BM, BATCH), 256, GEMM_SMEM>>>(
        att_h, VWt, Yout, SK, (long)SQ * SK, (long)DM * SK, (long)SQ * DM,
        bc, nullptr, 0.f, 0, 0, SK, SK, nullptr, nullptr);

    // ---- join replicate leg ----
    if (out_att && ok) cudaStreamWaitEvent(0, eB, 0);
}

// round 14
// speedup vs baseline: 1.2839x; 1.0926x over previous
#include <cuda_runtime.h>
#include <cuda_fp16.h>
#include <math.h>
#include <stdint.h>

// Problem constants
#define BATCH 8
#define SQ    1024
#define SK    1024
#define DM    512
#define NH    8

// ---------------- device scratch ----------------------------------------------
__device__ __half g_Qh[BATCH * SQ * DM];
__device__ __half g_Kh[BATCH * SK * DM];
__device__ __half g_Vh[BATCH * SK * DM];
__device__ __half g_Wqh[DM * DM];
__device__ __half g_Wkh[DM * DM];
__device__ __half g_Wvh[DM * DM];
__device__ __half g_M[DM * DM];              // M~ = Wq @ Wk^T (fp16)
__device__ __half g_Km[BATCH * SK * DM];     // K @ M~^T per batch
__device__ __half g_VWt[BATCH * DM * SK];    // (V @ Wc)^T per batch: [b][d][sk]
__device__ float  g_att[BATCH * SQ * SK];    // fp32 E = exp(scores)
__device__ __half g_att_h[BATCH * SQ * SK];  // fp16 normalized probs (final GEMM A)
__device__ float  g_rs[BATCH * SQ];          // per-row 1/sum
__device__ __half g_WleT[DM * DM];
__device__ __half g_WcT[DM * DM];
__device__ __half g_WcP[4 * DM * DM];        // shared split-K partials (M~ then WcT)
__device__ float  g_bc[DM];
__device__ float  g_wqbk[DM];
__device__ float  g_wkbq[DM];
__device__ float  g_a[BATCH * SQ];           // row bias for scores
__device__ float  g_b[BATCH * SK];           // col bias for scores
__device__ float  g_c[1];
__device__ float  g_zero = 0.f;              // never written

// ---------------- PTX helpers --------------------------------------------------
__device__ __forceinline__ uint32_t smem_u32(const void* p) {
    uint32_t a;
    asm("{ .reg .u64 t; cvta.to.shared.u64 t, %1; cvt.u32.u64 %0, t; }" : "=r"(a) : "l"(p));
    return a;
}

#define CP_ASYNC16(dst, src) \
    asm volatile("cp.async.cg.shared.global [%0], [%1], 16;" :: "r"(dst), "l"(src) : "memory")
#define CP_COMMIT() asm volatile("cp.async.commit_group;" ::: "memory")
#define CP_WAIT2()  asm volatile("cp.async.wait_group 2;" ::: "memory")
#define CP_WAIT1()  asm volatile("cp.async.wait_group 1;" ::: "memory")
#define CP_WAIT0()  asm volatile("cp.async.wait_group 0;" ::: "memory")

#define LDSM4(r0, r1, r2, r3, addr) \
    asm volatile("ldmatrix.sync.aligned.m8n8.x4.shared.b16 {%0,%1,%2,%3}, [%4];" \
        : "=r"(r0), "=r"(r1), "=r"(r2), "=r"(r3) : "r"(addr))

__device__ __forceinline__ void mma_f16(float* c, const uint32_t* a, const uint32_t* b) {
    asm volatile(
        "mma.sync.aligned.m16n8k16.row.col.f32.f16.f16.f32 "
        "{%0,%1,%2,%3}, {%4,%5,%6,%7}, {%8,%9}, {%0,%1,%2,%3};"
        : "+f"(c[0]), "+f"(c[1]), "+f"(c[2]), "+f"(c[3])
        : "r"(a[0]), "r"(a[1]), "r"(a[2]), "r"(a[3]), "r"(b[0]), "r"(b[1]));
}

// ================================================================================
// fp16 mma.sync GEMM: C[M,N] = A[M,K] @ B[N,K]^T   (fp32 accumulate)
// Block tile 256x128x32, 8 warps (4x2), warp tile 64x64, 3-stage cp.async ring,
// ldmatrix.x4 fragment loads (conflict-free with LDH=40 stride).
// MODE 0: C += bias[n]; output fp16 if OUT_HALF else fp32
// MODE 1: C = exp(C*scale + rowb[bz*SQ+m] + colb[bz*SK+n] + mask*-1e9)  (fp32 E out)
// MODE 2: transposed fp16 store: out[b2*foldT + n*ldT + mloc]
// grid (N/128, M/256, batches-or-ksplits), 256 threads
// ================================================================================
#define BM 256
#define BN 128
#define BK 32
#define LDH 40
#define A_TILE_H (BM * LDH)                      // 10240
#define B_TILE_H (BN * LDH)                      // 5120
#define STAGE_H  (A_TILE_H + B_TILE_H)           // 15360
#define NSTAGE 3
#define GEMM_SMEM (NSTAGE * STAGE_H * 2)         // 92160 B

template <int MODE, int OUT_HALF>
__global__ void __launch_bounds__(256, 1) gemm_h(
    const __half* __restrict__ A, const __half* __restrict__ B, void* __restrict__ Cv,
    int Kdim, long sA, long sB, long sC,
    const float* __restrict__ bias, const int* __restrict__ mask, float scale,
    int ldT, long foldT, int lda, int ldb,
    const float* __restrict__ rowb, const float* __restrict__ colb)
{
    extern __shared__ __half smem[];
    const uint32_t smb = smem_u32(smem);

    const int tid = threadIdx.x;
    const int lane = tid & 31, wid = tid >> 5;
    const int g = lane >> 2, t = lane & 3;
    const int wm = wid >> 1, wn = wid & 1;       // 4 x 2 warps, warp tile 64x64
    const int m0 = blockIdx.y * BM, n0 = blockIdx.x * BN, bz = blockIdx.z;

    const __half* Ag = A + (long)bz * sA;
    const __half* Bg = B + (long)bz * sB;

    float acc[4][8][4];
#pragma unroll
    for (int i = 0; i < 4; i++)
#pragma unroll
        for (int j = 0; j < 8; j++)
#pragma unroll
            for (int r = 0; r < 4; r++) acc[i][j][r] = 0.f;

    const int NC = Kdim / BK;
    const int lrow = tid >> 2, lchunk = (tid & 3) * 8;   // cp.async slots

    const int lj = lane >> 3, lr8 = lane & 7;
    uint32_t aoff[4], boff[4];
#pragma unroll
    for (int mt = 0; mt < 4; mt++)
        aoff[mt] = (uint32_t)(((wm * 64 + mt * 16 + lr8 + 8 * (lj & 1)) * LDH
                               + 8 * (lj >> 1)) * 2);
#pragma unroll
    for (int np = 0; np < 4; np++)
        boff[np] = (uint32_t)((A_TILE_H + (wn * 64 + np * 16 + lr8 + 8 * (lj >> 1)) * LDH
                               + 8 * (lj & 1)) * 2);

    auto issue = [&](int c, int s) {
        const long k0 = (long)c * BK;
        const uint32_t abase = smb + (uint32_t)(s * STAGE_H * 2);
        const uint32_t bbase = abase + (uint32_t)(A_TILE_H * 2);
#pragma unroll
        for (int j = 0; j < 4; j++) {
            int row = lrow + 64 * j;
            CP_ASYNC16(abase + (uint32_t)((row * LDH + lchunk) * 2),
                       Ag + (long)(m0 + row) * lda + k0 + lchunk);
        }
#pragma unroll
        for (int j = 0; j < 2; j++) {
            int row = lrow + 64 * j;
            CP_ASYNC16(bbase + (uint32_t)((row * LDH + lchunk) * 2),
                       Bg + (long)(n0 + row) * ldb + k0 + lchunk);
        }
        CP_COMMIT();
    };

    issue(0, 0);
    if (NC > 1) issue(1, 1);

    for (int c = 0; c < NC; c++) {
        const int buf = c % NSTAGE;
        if (c + 2 < NC) { issue(c + 2, (c + 2) % NSTAGE); CP_WAIT2(); }
        else if (c + 1 < NC) { CP_WAIT1(); }
        else { CP_WAIT0(); }
        __syncthreads();

        const uint32_t sbase = smb + (uint32_t)(buf * STAGE_H * 2);

#pragma unroll
        for (int kk = 0; kk < 2; kk++) {
            const uint32_t kboff = (uint32_t)(kk * 16 * 2);
            uint32_t af[4][4], bf[8][2];
#pragma unroll
            for (int mt = 0; mt < 4; mt++)
                LDSM4(af[mt][0], af[mt][1], af[mt][2], af[mt][3],
                      sbase + aoff[mt] + kboff);
#pragma unroll
            for (int np = 0; np < 4; np++)
                LDSM4(bf[2 * np][0], bf[2 * np][1], bf[2 * np + 1][0], bf[2 * np + 1][1],
                      sbase + boff[np] + kboff);
#pragma unroll
            for (int mt = 0; mt < 4; mt++)
#pragma unroll
                for (int nt = 0; nt < 8; nt++)
                    mma_f16(acc[mt][nt], af[mt], bf[nt]);
        }
        __syncthreads();
    }

    // ---- epilogue ----
    if (MODE == 2) {
        __half* Cz = (__half*)Cv + (long)bz * sC;
        __half* stage = smem;                    // [128][264] halves (n x m)
#pragma unroll
        for (int mt = 0; mt < 4; mt++) {
            const int r0 = wm * 64 + mt * 16 + g;
#pragma unroll
            for (int nt = 0; nt < 8; nt++) {
                const int c0 = wn * 64 + nt * 8 + t * 2;
                stage[(c0    ) * 264 + r0    ] = __float2half_rn(acc[mt][nt][0]);
                stage[(c0 + 1) * 264 + r0    ] = __float2half_rn(acc[mt][nt][1]);
                stage[(c0    ) * 264 + r0 + 8] = __float2half_rn(acc[mt][nt][2]);
                stage[(c0 + 1) * 264 + r0 + 8] = __float2half_rn(acc[mt][nt][3]);
            }
        }
        __syncthreads();
        const int b2 = m0 >> 10, mq = tid & 63, rq = tid >> 6;
        const int mloc = (m0 & 1023) + mq * 4;
#pragma unroll
        for (int it = 0; it < 32; it++) {
            const int nr = rq + it * 4;
            uint2 v = *(const uint2*)&stage[nr * 264 + mq * 4];
            *(uint2*)&Cz[(long)b2 * foldT + (long)(n0 + nr) * ldT + mloc] = v;
        }
        return;
    }

    const int ldc = gridDim.x * BN;
#pragma unroll
    for (int mt = 0; mt < 4; mt++) {
        const int r0 = m0 + wm * 64 + mt * 16 + g;
#pragma unroll
        for (int nt = 0; nt < 8; nt++) {
            const int c0 = n0 + wn * 64 + nt * 8 + t * 2;
            float2 v0 = { acc[mt][nt][0], acc[mt][nt][1] };
            float2 v1 = { acc[mt][nt][2], acc[mt][nt][3] };
            if (MODE == 0) {
                if (bias) {
                    v0.x += bias[c0]; v0.y += bias[c0 + 1];
                    v1.x += bias[c0]; v1.y += bias[c0 + 1];
                }
                if (OUT_HALF) {
                    __half* Cg = (__half*)Cv + (long)bz * sC;
                    *(__half2*)&Cg[(long)r0 * ldc + c0]       = __floats2half2_rn(v0.x, v0.y);
                    *(__half2*)&Cg[(long)(r0 + 8) * ldc + c0] = __floats2half2_rn(v1.x, v1.y);
                    continue;
                }
            } else { // MODE 1: scale + rank-1 bias + mask, then exp (fp32 E)
                const int* mk = mask + (long)bz * SK;
                float p0 = mk[c0] ? -1e9f : 0.f, p1 = mk[c0 + 1] ? -1e9f : 0.f;
                float ra  = rowb[(long)bz * SQ + r0];
                float ra8 = rowb[(long)bz * SQ + r0 + 8];
                float cb0 = colb[(long)bz * SK + c0];
                float cb1 = colb[(long)bz * SK + c0 + 1];
                v0.x = expf(v0.x * scale + ra  + cb0 + p0);
                v0.y = expf(v0.y * scale + ra  + cb1 + p1);
                v1.x = expf(v1.x * scale + ra8 + cb0 + p0);
                v1.y = expf(v1.y * scale + ra8 + cb1 + p1);
            }
            float* Cg = (float*)Cv + (long)bz * sC;
            *(float2*)&Cg[(long)r0 * ldc + c0]       = v0;
            *(float2*)&Cg[(long)(r0 + 8) * ldc + c0] = v1;
        }
    }
}

// ================================================================================
// helper kernels
// ================================================================================
__global__ void f32_to_f16(const float* __restrict__ in, __half* __restrict__ out) {
    long i = ((long)blockIdx.x * 256 + threadIdx.x) * 4;
    float4 v = *(const float4*)&in[i];
    __half2 h0 = __floats2half2_rn(v.x, v.y);
    __half2 h1 = __floats2half2_rn(v.z, v.w);
    uint2 p = { *(uint32_t*)&h0, *(uint32_t*)&h1 };
    *(uint2*)&out[i] = p;
}

__global__ void wl_sumT_tiled(const float* __restrict__ Wl, __half* __restrict__ WleT) {
    __shared__ float t[32][33];
    int bx = blockIdx.x * 32, by = blockIdx.y * 32;
    for (int i = threadIdx.y; i < 32; i += 8) {
        float s = 0.f;
#pragma unroll
        for (int h = 0; h < NH; h++)
            s += Wl[((long)(h * DM) + by + i) * DM + bx + threadIdx.x];
        t[i][threadIdx.x] = s;
    }
    __syncthreads();
    for (int i = threadIdx.y; i < 32; i += 8)
        WleT[(bx + i) * DM + by + threadIdx.x] = __float2half_rn(t[threadIdx.x][i]);
}

__global__ void bc_kernel(const float* __restrict__ bl, const float* __restrict__ bv,
                          const __half* __restrict__ WleT, float* __restrict__ bc) {
    const int n = blockIdx.x, t = threadIdx.x;
    __shared__ float red[256];
    float s = 0.f;
    for (int k = t; k < DM; k += 256) s += bv[k] * __half2float(WleT[n * DM + k]);
    red[t] = s;
    __syncthreads();
#pragma unroll
    for (int o = 128; o >= 32; o >>= 1) {
        if (t < o) red[t] += red[t + o];
        __syncthreads();
    }
    if (t < 32) {
        float v = red[t];
#pragma unroll
        for (int o = 16; o > 0; o >>= 1)
            v += __shfl_down_sync(0xffffffffu, v, o);
        if (t == 0) bc[n] = bl[n] + v;
    }
}

__global__ void dot512(const float* __restrict__ a, const float* __restrict__ b,
                       float* __restrict__ out) {
    const int t = threadIdx.x;
    __shared__ float red[256];
    float s = 0.f;
    for (int k = t; k < DM; k += 256) s += a[k] * b[k];
    red[t] = s;
    __syncthreads();
#pragma unroll
    for (int o = 128; o >= 32; o >>= 1) {
        if (t < o) red[t] += red[t + o];
        __syncthreads();
    }
    if (t < 32) {
        float v = red[t];
#pragma unroll
        for (int o = 16; o > 0; o >>= 1)
            v += __shfl_down_sync(0xffffffffu, v, o);
        if (t == 0) out[0] = v;
    }
}

__global__ void vecdot512(const float* __restrict__ W, const float* __restrict__ v,
                          float* __restrict__ out) {
    const int f = blockIdx.x, t = threadIdx.x;
    __shared__ float red[128];
    float s = 0.f;
    for (int k = t; k < DM; k += 128) s += W[(long)f * DM + k] * v[k];
    red[t] = s;
    __syncthreads();
#pragma unroll
    for (int o = 64; o >= 32; o >>= 1) {
        if (t < o) red[t] += red[t + o];
        __syncthreads();
    }
    if (t < 32) {
        float x = red[t];
#pragma unroll
        for (int o = 16; o > 0; o >>= 1)
            x += __shfl_down_sync(0xffffffffu, x, o);
        if (t == 0) out[f] = x;
    }
}

__global__ void rowdot(const float* __restrict__ X, const float* __restrict__ vec,
                       const float* __restrict__ cadd, float* __restrict__ out,
                       float scale) {
    const int r = blockIdx.x, t = threadIdx.x;
    __shared__ float red[128];
    float s = 0.f;
    for (int k = t; k < DM; k += 128) s += X[(long)r * DM + k] * vec[k];
    red[t] = s;
    __syncthreads();
#pragma unroll
    for (int o = 64; o >= 32; o >>= 1) {
        if (t < o) red[t] += red[t + o];
        __syncthreads();
    }
    if (t < 32) {
        float x = red[t];
#pragma unroll
        for (int o = 16; o > 0; o >>= 1)
            x += __shfl_down_sync(0xffffffffu, x, o);
        if (t == 0) out[r] = (x + cadd[0]) * scale;
    }
}

__global__ void reduce4(const __half* __restrict__ p, __half* __restrict__ o) {
    long i = ((long)blockIdx.x * 256 + threadIdx.x) * 4;
    float s[4];
#pragma unroll
    for (int j = 0; j < 4; j++) s[j] = 0.f;
#pragma unroll
    for (int part = 0; part < 4; part++) {
        uint2 v = *(const uint2*)&p[(long)part * DM * DM + i];
        __half2 h0 = *(__half2*)&v.x, h1 = *(__half2*)&v.y;
        s[0] += __low2float(h0);  s[1] += __high2float(h0);
        s[2] += __low2float(h1);  s[3] += __high2float(h1);
    }
    __half2 r0 = __floats2half2_rn(s[0], s[1]);
    __half2 r1 = __floats2half2_rn(s[2], s[3]);
    uint2 r = { *(uint32_t*)&r0, *(uint32_t*)&r1 };
    *(uint2*)&o[i] = r;
}

// row-normalize: read fp32 E, write fp16 probs + per-row inverse sum
__global__ void normsum(const float* __restrict__ E, __half* __restrict__ att_h,
                        float* __restrict__ rinv) {
    const int q = blockIdx.x, b = blockIdx.y, t = threadIdx.x;
    const float* row = E + ((long)(b * SQ + q)) * SK;
    float4 v = ((const float4*)row)[t];

    __shared__ float red[256];
    red[t] = v.x + v.y + v.z + v.w;
    __syncthreads();
#pragma unroll
    for (int s = 128; s > 0; s >>= 1) {
        if (t < s) red[t] += red[t + s];
        __syncthreads();
    }
    const float r = 1.0f / red[0];

    float4 p = { v.x * r, v.y * r, v.z * r, v.w * r };
    __half2 h0 = __floats2half2_rn(p.x, p.y);
    __half2 h1 = __floats2half2_rn(p.z, p.w);
    uint2 ph = { *(uint32_t*)&h0, *(uint32_t*)&h1 };
    ((uint2*)(att_h + ((long)(b * SQ + q)) * SK))[t] = ph;

    if (t == 0) rinv[b * SQ + q] = r;
}

// write all 8 fp32 prob replicas from fp32 E + rinv (pure HBM, overlaps final GEMM)
__global__ void replicate8(const float* __restrict__ E, const float* __restrict__ rinv,
                           float* __restrict__ out_att) {
    const int q = blockIdx.x, b = blockIdx.y, t = threadIdx.x;
    const float r = rinv[b * SQ + q];
    float4 v = ((const float4*)(E + ((long)(b * SQ + q)) * SK))[t];
    v.x *= r; v.y *= r; v.z *= r; v.w *= r;
#pragma unroll
    for (int h = 0; h < NH; h++)
        ((float4*)(out_att + (((long)(b * NH + h) * SQ) + q) * SK))[t] = v;
}

// ================================================================================
// launch
// ================================================================================
extern "C" void kernel_launch(void* const* d_in, const int* in_sizes, int n_in,
                              void* d_out, int out_size) {
    const float* Q    = (const float*)d_in[0];
    const float* K    = (const float*)d_in[1];
    const float* V    = (const float*)d_in[2];
    const int*   mask = (const int*)  d_in[3];
    const float* Wq   = (const float*)d_in[4];
    const float* bq   = (const float*)d_in[5];
    const float* Wk   = (const float*)d_in[6];
    const float* bk   = (const float*)d_in[7];
    const float* Wv   = (const float*)d_in[8];
    const float* bv   = (const float*)d_in[9];
    const float* Wl   = (const float*)d_in[10];
    const float* bl   = (const float*)d_in[11];

    __half *Qh, *Kh, *Vh, *Wqh, *Wkh, *Wvh, *Mh, *Km, *VWt, *att_h, *wleT, *wcT, *wcP;
    float *att, *rs, *bc, *wqbk, *wkbq, *av, *bvv, *cs, *zs;
    cudaGetSymbolAddress((void**)&Qh,    g_Qh);
    cudaGetSymbolAddress((void**)&Kh,    g_Kh);
    cudaGetSymbolAddress((void**)&Vh,    g_Vh);
    cudaGetSymbolAddress((void**)&Wqh,   g_Wqh);
    cudaGetSymbolAddress((void**)&Wkh,   g_Wkh);
    cudaGetSymbolAddress((void**)&Wvh,   g_Wvh);
    cudaGetSymbolAddress((void**)&Mh,    g_M);
    cudaGetSymbolAddress((void**)&Km,    g_Km);
    cudaGetSymbolAddress((void**)&VWt,   g_VWt);
    cudaGetSymbolAddress((void**)&att,   g_att);
    cudaGetSymbolAddress((void**)&att_h, g_att_h);
    cudaGetSymbolAddress((void**)&rs,    g_rs);
    cudaGetSymbolAddress((void**)&wleT,  g_WleT);
    cudaGetSymbolAddress((void**)&wcT,   g_WcT);
    cudaGetSymbolAddress((void**)&wcP,   g_WcP);
    cudaGetSymbolAddress((void**)&bc,    g_bc);
    cudaGetSymbolAddress((void**)&wqbk,  g_wqbk);
    cudaGetSymbolAddress((void**)&wkbq,  g_wkbq);
    cudaGetSymbolAddress((void**)&av,    g_a);
    cudaGetSymbolAddress((void**)&bvv,   g_b);
    cudaGetSymbolAddress((void**)&cs,    g_c);
    cudaGetSymbolAddress((void**)&zs,    g_zero);

    float* Yout = (float*)d_out;
    const long YSIZE = (long)BATCH * SQ * DM;
    const long ASIZE = (long)BATCH * NH * SQ * SK;
    float* out_att = ((long)out_size >= YSIZE + ASIZE) ? (Yout + YSIZE) : nullptr;
    const float inv_scale = 1.0f / sqrtf((float)DM);

    cudaFuncSetAttribute(gemm_h<0,0>, cudaFuncAttributeMaxDynamicSharedMemorySize, GEMM_SMEM);
    cudaFuncSetAttribute(gemm_h<0,1>, cudaFuncAttributeMaxDynamicSharedMemorySize, GEMM_SMEM);
    cudaFuncSetAttribute(gemm_h<1,0>, cudaFuncAttributeMaxDynamicSharedMemorySize, GEMM_SMEM);
    cudaFuncSetAttribute(gemm_h<2,1>, cudaFuncAttributeMaxDynamicSharedMemorySize, GEMM_SMEM);

    // lazily-created side streams + events (capture-safe; no device allocs)
    static cudaStream_t sA = nullptr, sB = nullptr;
    static cudaEvent_t  e0 = nullptr, eKc = nullptr, eR = nullptr, eVp = nullptr,
                        eK = nullptr, eA = nullptr, eN = nullptr, eB = nullptr;
    if (!sA) {
        cudaStreamCreateWithFlags(&sA, cudaStreamNonBlocking);
        cudaStreamCreateWithFlags(&sB, cudaStreamNonBlocking);
        cudaEventCreateWithFlags(&e0,  cudaEventDisableTiming);
        cudaEventCreateWithFlags(&eKc, cudaEventDisableTiming);
        cudaEventCreateWithFlags(&eR,  cudaEventDisableTiming);
        cudaEventCreateWithFlags(&eVp, cudaEventDisableTiming);
        cudaEventCreateWithFlags(&eK,  cudaEventDisableTiming);
        cudaEventCreateWithFlags(&eA,  cudaEventDisableTiming);
        cudaEventCreateWithFlags(&eN,  cudaEventDisableTiming);
        cudaEventCreateWithFlags(&eB,  cudaEventDisableTiming);
    }
    const bool ok = (sA && sB && e0 && eKc && eR && eVp && eK && eA && eN && eB);
    cudaStream_t wA = ok ? sA : (cudaStream_t)0;   // weight/K tensor leg
    cudaStream_t wB = ok ? sB : (cudaStream_t)0;   // helpers / V-prep / replicate leg

    const int NBIG = (BATCH * SQ * DM) / 1024;
    const int NSML = (DM * DM) / 1024;

    if (ok) {
        cudaEventRecord(e0, 0);
        cudaStreamWaitEvent(wA, e0, 0);
        cudaStreamWaitEvent(wB, e0, 0);
    }

    // ---- stream0: K convert first (gates Km), then Q convert ----
    f32_to_f16<<<NBIG, 256>>>(K, Kh);
    if (ok) cudaEventRecord(eKc, 0);
    f32_to_f16<<<NBIG, 256>>>(Q, Qh);

    // ---- streamB: rank-1 precomputes, then V-prep small kernels ----
    dot512<<<1, 256, 0, wB>>>(bq, bk, cs);
    vecdot512<<<DM, 128, 0, wB>>>(Wq, bk, wqbk);
    vecdot512<<<DM, 128, 0, wB>>>(Wk, bq, wkbq);
    rowdot<<<BATCH * SQ, 128, 0, wB>>>(Q, wqbk, cs, av, inv_scale);
    rowdot<<<BATCH * SK, 128, 0, wB>>>(K, wkbq, zs, bvv, inv_scale);
    if (ok) cudaEventRecord(eR, wB);
    f32_to_f16<<<NBIG, 256, 0, wB>>>(V, Vh);
    f32_to_f16<<<NSML, 256, 0, wB>>>(Wv, Wvh);
    wl_sumT_tiled<<<dim3(16, 16), dim3(32, 8), 0, wB>>>(Wl, wleT);
    bc_kernel<<<DM, 256, 0, wB>>>(bl, bv, wleT, bc);
    if (ok) cudaEventRecord(eVp, wB);

    // ---- streamA: M~ then Km (full batch), then WcT / VWt ----
    f32_to_f16<<<NSML, 256, 0, wA>>>(Wq, Wqh);
    f32_to_f16<<<NSML, 256, 0, wA>>>(Wk, Wkh);
    gemm_h<0,1><<<dim3(DM / BN, DM / BM, 4), 256, GEMM_SMEM, wA>>>(
        Wqh, Wkh, wcP, 128, 128, 128, (long)DM * DM,
        nullptr, nullptr, 0.f, 0, 0, DM, DM, nullptr, nullptr);
    reduce4<<<DM * DM / 1024, 256, 0, wA>>>(wcP, Mh);
    if (ok) cudaStreamWaitEvent(wA, eKc, 0);
    gemm_h<0,1><<<dim3(DM / BN, (BATCH * SK) / BM, 1), 256, GEMM_SMEM, wA>>>(
        Kh, Mh, Km, DM, 0, 0, 0, nullptr, nullptr, 0.f, 0, 0, DM, DM, nullptr, nullptr);
    if (ok) cudaEventRecord(eK, wA);
    if (ok) cudaStreamWaitEvent(wA, eVp, 0);
    gemm_h<2,1><<<dim3(DM / BN, DM / BM, 4), 256, GEMM_SMEM, wA>>>(
        Wvh, wleT, wcP, 128, 128, 128, (long)DM * DM,
        nullptr, nullptr, 0.f, DM, 0, DM, DM, nullptr, nullptr);
    reduce4<<<DM * DM / 1024, 256, 0, wA>>>(wcP, wcT);
    gemm_h<2,1><<<dim3(DM / BN, (BATCH * SK) / BM, 1), 256, GEMM_SMEM, wA>>>(
        Vh, wcT, VWt, DM, 0, 0, 0, nullptr, nullptr, 0.f, SK, (long)DM * SK, DM, DM,
        nullptr, nullptr);
    if (ok) cudaEventRecord(eA, wA);

    // ---- stream0: E = exp(scores) fused; then row-normalize ----
    if (ok) { cudaStreamWaitEvent(0, eK, 0); cudaStreamWaitEvent(0, eR, 0); }
    gemm_h<1,0><<<dim3(SK / BN, SQ / BM, BATCH), 256, GEMM_SMEM>>>(
        Qh, Km, att, DM, (long)SQ * DM, (long)SK * DM, (long)SQ * SK,
        nullptr, mask, inv_scale, 0, 0, DM, DM, av, bvv);
    normsum<<<dim3(SQ, BATCH), 256>>>(att, att_h, rs);

    // ---- fork replicate leg (8 fp32 replicas from E + rinv) ----
    if (out_att) {
        if (ok) {
            cudaEventRecord(eN, 0);
            cudaStreamWaitEvent(wB, eN, 0);
        }
        replicate8<<<dim3(SQ, BATCH), 256, 0, wB>>>(att, rs, out_att);
        if (ok) cudaEventRecord(eB, wB);
    }

    // ---- join leg A; final GEMM ----
    if (ok) cudaStreamWaitEvent(0, eA, 0);
    gemm_h<0,0><<<dim3(DM / BN, SQ / BM, BATCH), 256, GEMM_SMEM>>>(
        att_h, VWt, Yout, SK, (long)SQ * SK, (long)DM * SK, (long)SQ * DM,
        bc, nullptr, 0.f, 0, 0, SK, SK, nullptr, nullptr);

    // ---- join replicate leg ----
    if (out_att && ok) cudaStreamWaitEvent(0, eB, 0);
}

// round 15
// speedup vs baseline: 1.3020x; 1.0141x over previous
#include <cuda_runtime.h>
#include <cuda_fp16.h>
#include <math.h>
#include <stdint.h>

// Problem constants
#define BATCH 8
#define SQ    1024
#define SK    1024
#define DM    512
#define NH    8

// ---------------- device scratch ----------------------------------------------
__device__ __half g_Qh[BATCH * SQ * DM];
__device__ __half g_Kh[BATCH * SK * DM];
__device__ __half g_Vh[BATCH * SK * DM];
__device__ __half g_Wqh[DM * DM];
__device__ __half g_Wkh[DM * DM];
__device__ __half g_Wvh[DM * DM];
__device__ __half g_M[DM * DM];              // M~ = Wq @ Wk^T (fp16)
__device__ __half g_Km[BATCH * SK * DM];     // K @ M~^T per batch
__device__ __half g_VWt[BATCH * DM * SK];    // (V @ Wc)^T per batch: [b][d][sk]
__device__ __half g_Eh[BATCH * SQ * SK];     // fp16 E = exp(scores), unnormalized
__device__ float  g_rs[BATCH * SQ];          // per-row 1/sum(E)
__device__ __half g_WleT[DM * DM];
__device__ __half g_WcT[DM * DM];
__device__ __half g_WcP[4 * DM * DM];        // shared split-K partials (M~ then WcT)
__device__ float  g_bc[DM];
__device__ float  g_wqbk[DM];
__device__ float  g_wkbq[DM];
__device__ float  g_a[BATCH * SQ];           // row bias for scores
__device__ float  g_b[BATCH * SK];           // col bias for scores
__device__ float  g_c[1];
__device__ float  g_zero = 0.f;              // never written

// ---------------- PTX helpers --------------------------------------------------
__device__ __forceinline__ uint32_t smem_u32(const void* p) {
    uint32_t a;
    asm("{ .reg .u64 t; cvta.to.shared.u64 t, %1; cvt.u32.u64 %0, t; }" : "=r"(a) : "l"(p));
    return a;
}

#define CP_ASYNC16(dst, src) \
    asm volatile("cp.async.cg.shared.global [%0], [%1], 16;" :: "r"(dst), "l"(src) : "memory")
#define CP_COMMIT() asm volatile("cp.async.commit_group;" ::: "memory")
#define CP_WAIT2()  asm volatile("cp.async.wait_group 2;" ::: "memory")
#define CP_WAIT1()  asm volatile("cp.async.wait_group 1;" ::: "memory")
#define CP_WAIT0()  asm volatile("cp.async.wait_group 0;" ::: "memory")

#define LDSM4(r0, r1, r2, r3, addr) \
    asm volatile("ldmatrix.sync.aligned.m8n8.x4.shared.b16 {%0,%1,%2,%3}, [%4];" \
        : "=r"(r0), "=r"(r1), "=r"(r2), "=r"(r3) : "r"(addr))

__device__ __forceinline__ void mma_f16(float* c, const uint32_t* a, const uint32_t* b) {
    asm volatile(
        "mma.sync.aligned.m16n8k16.row.col.f32.f16.f16.f32 "
        "{%0,%1,%2,%3}, {%4,%5,%6,%7}, {%8,%9}, {%0,%1,%2,%3};"
        : "+f"(c[0]), "+f"(c[1]), "+f"(c[2]), "+f"(c[3])
        : "r"(a[0]), "r"(a[1]), "r"(a[2]), "r"(a[3]), "r"(b[0]), "r"(b[1]));
}

// ================================================================================
// fp16 mma.sync GEMM: C[M,N] = A[M,K] @ B[N,K]^T   (fp32 accumulate)
// Block tile 256x128x32, 8 warps (4x2), warp tile 64x64, 3-stage cp.async ring,
// ldmatrix.x4 fragment loads (conflict-free with LDH=40 stride).
// MODE 0: C = acc * rowb[bz*SQ+m] (if rowb) + bias[n]; fp16 out if OUT_HALF
// MODE 1: C = fp16( exp(acc*scale + rowb[m] + colb[n] + mask*-1e9) )  (fp16 E out)
// MODE 2: transposed fp16 store: out[b2*foldT + n*ldT + mloc]
// grid (N/128, M/256, batches-or-ksplits), 256 threads
// ================================================================================
#define BM 256
#define BN 128
#define BK 32
#define LDH 40
#define A_TILE_H (BM * LDH)                      // 10240
#define B_TILE_H (BN * LDH)                      // 5120
#define STAGE_H  (A_TILE_H + B_TILE_H)           // 15360
#define NSTAGE 3
#define GEMM_SMEM (NSTAGE * STAGE_H * 2)         // 92160 B

template <int MODE, int OUT_HALF>
__global__ void __launch_bounds__(256, 1) gemm_h(
    const __half* __restrict__ A, const __half* __restrict__ B, void* __restrict__ Cv,
    int Kdim, long sA, long sB, long sC,
    const float* __restrict__ bias, const int* __restrict__ mask, float scale,
    int ldT, long foldT, int lda, int ldb,
    const float* __restrict__ rowb, const float* __restrict__ colb)
{
    extern __shared__ __half smem[];
    const uint32_t smb = smem_u32(smem);

    const int tid = threadIdx.x;
    const int lane = tid & 31, wid = tid >> 5;
    const int g = lane >> 2, t = lane & 3;
    const int wm = wid >> 1, wn = wid & 1;       // 4 x 2 warps, warp tile 64x64
    const int m0 = blockIdx.y * BM, n0 = blockIdx.x * BN, bz = blockIdx.z;

    const __half* Ag = A + (long)bz * sA;
    const __half* Bg = B + (long)bz * sB;

    float acc[4][8][4];
#pragma unroll
    for (int i = 0; i < 4; i++)
#pragma unroll
        for (int j = 0; j < 8; j++)
#pragma unroll
            for (int r = 0; r < 4; r++) acc[i][j][r] = 0.f;

    const int NC = Kdim / BK;
    const int lrow = tid >> 2, lchunk = (tid & 3) * 8;   // cp.async slots

    const int lj = lane >> 3, lr8 = lane & 7;
    uint32_t aoff[4], boff[4];
#pragma unroll
    for (int mt = 0; mt < 4; mt++)
        aoff[mt] = (uint32_t)(((wm * 64 + mt * 16 + lr8 + 8 * (lj & 1)) * LDH
                               + 8 * (lj >> 1)) * 2);
#pragma unroll
    for (int np = 0; np < 4; np++)
        boff[np] = (uint32_t)((A_TILE_H + (wn * 64 + np * 16 + lr8 + 8 * (lj >> 1)) * LDH
                               + 8 * (lj & 1)) * 2);

    auto issue = [&](int c, int s) {
        const long k0 = (long)c * BK;
        const uint32_t abase = smb + (uint32_t)(s * STAGE_H * 2);
        const uint32_t bbase = abase + (uint32_t)(A_TILE_H * 2);
#pragma unroll
        for (int j = 0; j < 4; j++) {
            int row = lrow + 64 * j;
            CP_ASYNC16(abase + (uint32_t)((row * LDH + lchunk) * 2),
                       Ag + (long)(m0 + row) * lda + k0 + lchunk);
        }
#pragma unroll
        for (int j = 0; j < 2; j++) {
            int row = lrow + 64 * j;
            CP_ASYNC16(bbase + (uint32_t)((row * LDH + lchunk) * 2),
                       Bg + (long)(n0 + row) * ldb + k0 + lchunk);
        }
        CP_COMMIT();
    };

    issue(0, 0);
    if (NC > 1) issue(1, 1);

    for (int c = 0; c < NC; c++) {
        const int buf = c % NSTAGE;
        if (c + 2 < NC) { issue(c + 2, (c + 2) % NSTAGE); CP_WAIT2(); }
        else if (c + 1 < NC) { CP_WAIT1(); }
        else { CP_WAIT0(); }
        __syncthreads();

        const uint32_t sbase = smb + (uint32_t)(buf * STAGE_H * 2);

#pragma unroll
        for (int kk = 0; kk < 2; kk++) {
            const uint32_t kboff = (uint32_t)(kk * 16 * 2);
            uint32_t af[4][4], bf[8][2];
#pragma unroll
            for (int mt = 0; mt < 4; mt++)
                LDSM4(af[mt][0], af[mt][1], af[mt][2], af[mt][3],
                      sbase + aoff[mt] + kboff);
#pragma unroll
            for (int np = 0; np < 4; np++)
                LDSM4(bf[2 * np][0], bf[2 * np][1], bf[2 * np + 1][0], bf[2 * np + 1][1],
                      sbase + boff[np] + kboff);
#pragma unroll
            for (int mt = 0; mt < 4; mt++)
#pragma unroll
                for (int nt = 0; nt < 8; nt++)
                    mma_f16(acc[mt][nt], af[mt], bf[nt]);
        }
        __syncthreads();
    }

    // ---- epilogue ----
    if (MODE == 2) {
        __half* Cz = (__half*)Cv + (long)bz * sC;
        __half* stage = smem;                    // [128][264] halves (n x m)
#pragma unroll
        for (int mt = 0; mt < 4; mt++) {
            const int r0 = wm * 64 + mt * 16 + g;
#pragma unroll
            for (int nt = 0; nt < 8; nt++) {
                const int c0 = wn * 64 + nt * 8 + t * 2;
                stage[(c0    ) * 264 + r0    ] = __float2half_rn(acc[mt][nt][0]);
                stage[(c0 + 1) * 264 + r0    ] = __float2half_rn(acc[mt][nt][1]);
                stage[(c0    ) * 264 + r0 + 8] = __float2half_rn(acc[mt][nt][2]);
                stage[(c0 + 1) * 264 + r0 + 8] = __float2half_rn(acc[mt][nt][3]);
            }
        }
        __syncthreads();
        const int b2 = m0 >> 10, mq = tid & 63, rq = tid >> 6;
        const int mloc = (m0 & 1023) + mq * 4;
#pragma unroll
        for (int it = 0; it < 32; it++) {
            const int nr = rq + it * 4;
            uint2 v = *(const uint2*)&stage[nr * 264 + mq * 4];
            *(uint2*)&Cz[(long)b2 * foldT + (long)(n0 + nr) * ldT + mloc] = v;
        }
        return;
    }

    const int ldc = gridDim.x * BN;
#pragma unroll
    for (int mt = 0; mt < 4; mt++) {
        const int r0 = m0 + wm * 64 + mt * 16 + g;
#pragma unroll
        for (int nt = 0; nt < 8; nt++) {
            const int c0 = n0 + wn * 64 + nt * 8 + t * 2;
            float2 v0 = { acc[mt][nt][0], acc[mt][nt][1] };
            float2 v1 = { acc[mt][nt][2], acc[mt][nt][3] };
            if (MODE == 0) {
                if (rowb) {
                    const float rr0 = rowb[(long)bz * SQ + r0];
                    const float rr8 = rowb[(long)bz * SQ + r0 + 8];
                    v0.x *= rr0; v0.y *= rr0;
                    v1.x *= rr8; v1.y *= rr8;
                }
                if (bias) {
                    v0.x += bias[c0]; v0.y += bias[c0 + 1];
                    v1.x += bias[c0]; v1.y += bias[c0 + 1];
                }
                if (OUT_HALF) {
                    __half* Cg = (__half*)Cv + (long)bz * sC;
                    *(__half2*)&Cg[(long)r0 * ldc + c0]       = __floats2half2_rn(v0.x, v0.y);
                    *(__half2*)&Cg[(long)(r0 + 8) * ldc + c0] = __floats2half2_rn(v1.x, v1.y);
                    continue;
                }
                float* Cg = (float*)Cv + (long)bz * sC;
                *(float2*)&Cg[(long)r0 * ldc + c0]       = v0;
                *(float2*)&Cg[(long)(r0 + 8) * ldc + c0] = v1;
            } else { // MODE 1: scale + rank-1 bias + mask, exp, fp16 E store
                const int* mk = mask + (long)bz * SK;
                float p0 = mk[c0] ? -1e9f : 0.f, p1 = mk[c0 + 1] ? -1e9f : 0.f;
                float ra  = rowb[(long)bz * SQ + r0];
                float ra8 = rowb[(long)bz * SQ + r0 + 8];
                float cb0 = colb[(long)bz * SK + c0];
                float cb1 = colb[(long)bz * SK + c0 + 1];
                float e00 = expf(v0.x * scale + ra  + cb0 + p0);
                float e01 = expf(v0.y * scale + ra  + cb1 + p1);
                float e10 = expf(v1.x * scale + ra8 + cb0 + p0);
                float e11 = expf(v1.y * scale + ra8 + cb1 + p1);
                __half* Cg = (__half*)Cv + (long)bz * sC;
                *(__half2*)&Cg[(long)r0 * ldc + c0]       = __floats2half2_rn(e00, e01);
                *(__half2*)&Cg[(long)(r0 + 8) * ldc + c0] = __floats2half2_rn(e10, e11);
            }
        }
    }
}

// ================================================================================
// helper kernels
// ================================================================================
__global__ void f32_to_f16(const float* __restrict__ in, __half* __restrict__ out) {
    long i = ((long)blockIdx.x * 256 + threadIdx.x) * 4;
    float4 v = *(const float4*)&in[i];
    __half2 h0 = __floats2half2_rn(v.x, v.y);
    __half2 h1 = __floats2half2_rn(v.z, v.w);
    uint2 p = { *(uint32_t*)&h0, *(uint32_t*)&h1 };
    *(uint2*)&out[i] = p;
}

__global__ void wl_sumT_tiled(const float* __restrict__ Wl, __half* __restrict__ WleT) {
    __shared__ float t[32][33];
    int bx = blockIdx.x * 32, by = blockIdx.y * 32;
    for (int i = threadIdx.y; i < 32; i += 8) {
        float s = 0.f;
#pragma unroll
        for (int h = 0; h < NH; h++)
            s += Wl[((long)(h * DM) + by + i) * DM + bx + threadIdx.x];
        t[i][threadIdx.x] = s;
    }
    __syncthreads();
    for (int i = threadIdx.y; i < 32; i += 8)
        WleT[(bx + i) * DM + by + threadIdx.x] = __float2half_rn(t[threadIdx.x][i]);
}

__global__ void bc_kernel(const float* __restrict__ bl, const float* __restrict__ bv,
                          const __half* __restrict__ WleT, float* __restrict__ bc) {
    const int n = blockIdx.x, t = threadIdx.x;
    __shared__ float red[256];
    float s = 0.f;
    for (int k = t; k < DM; k += 256) s += bv[k] * __half2float(WleT[n * DM + k]);
    red[t] = s;
    __syncthreads();
#pragma unroll
    for (int o = 128; o >= 32; o >>= 1) {
        if (t < o) red[t] += red[t + o];
        __syncthreads();
    }
    if (t < 32) {
        float v = red[t];
#pragma unroll
        for (int o = 16; o > 0; o >>= 1)
            v += __shfl_down_sync(0xffffffffu, v, o);
        if (t == 0) bc[n] = bl[n] + v;
    }
}

__global__ void dot512(const float* __restrict__ a, const float* __restrict__ b,
                       float* __restrict__ out) {
    const int t = threadIdx.x;
    __shared__ float red[256];
    float s = 0.f;
    for (int k = t; k < DM; k += 256) s += a[k] * b[k];
    red[t] = s;
    __syncthreads();
#pragma unroll
    for (int o = 128; o >= 32; o >>= 1) {
        if (t < o) red[t] += red[t + o];
        __syncthreads();
    }
    if (t < 32) {
        float v = red[t];
#pragma unroll
        for (int o = 16; o > 0; o >>= 1)
            v += __shfl_down_sync(0xffffffffu, v, o);
        if (t == 0) out[0] = v;
    }
}

__global__ void vecdot512(const float* __restrict__ W, const float* __restrict__ v,
                          float* __restrict__ out) {
    const int f = blockIdx.x, t = threadIdx.x;
    __shared__ float red[128];
    float s = 0.f;
    for (int k = t; k < DM; k += 128) s += W[(long)f * DM + k] * v[k];
    red[t] = s;
    __syncthreads();
#pragma unroll
    for (int o = 64; o >= 32; o >>= 1) {
        if (t < o) red[t] += red[t + o];
        __syncthreads();
    }
    if (t < 32) {
        float x = red[t];
#pragma unroll
        for (int o = 16; o > 0; o >>= 1)
            x += __shfl_down_sync(0xffffffffu, x, o);
        if (t == 0) out[f] = x;
    }
}

__global__ void rowdot(const float* __restrict__ X, const float* __restrict__ vec,
                       const float* __restrict__ cadd, float* __restrict__ out,
                       float scale) {
    const int r = blockIdx.x, t = threadIdx.x;
    __shared__ float red[128];
    float s = 0.f;
    for (int k = t; k < DM; k += 128) s += X[(long)r * DM + k] * vec[k];
    red[t] = s;
    __syncthreads();
#pragma unroll
    for (int o = 64; o >= 32; o >>= 1) {
        if (t < o) red[t] += red[t + o];
        __syncthreads();
    }
    if (t < 32) {
        float x = red[t];
#pragma unroll
        for (int o = 16; o > 0; o >>= 1)
            x += __shfl_down_sync(0xffffffffu, x, o);
        if (t == 0) out[r] = (x + cadd[0]) * scale;
    }
}

__global__ void reduce4(const __half* __restrict__ p, __half* __restrict__ o) {
    long i = ((long)blockIdx.x * 256 + threadIdx.x) * 4;
    float s[4];
#pragma unroll
    for (int j = 0; j < 4; j++) s[j] = 0.f;
#pragma unroll
    for (int part = 0; part < 4; part++) {
        uint2 v = *(const uint2*)&p[(long)part * DM * DM + i];
        __half2 h0 = *(__half2*)&v.x, h1 = *(__half2*)&v.y;
        s[0] += __low2float(h0);  s[1] += __high2float(h0);
        s[2] += __low2float(h1);  s[3] += __high2float(h1);
    }
    __half2 r0 = __floats2half2_rn(s[0], s[1]);
    __half2 r1 = __floats2half2_rn(s[2], s[3]);
    uint2 r = { *(uint32_t*)&r0, *(uint32_t*)&r1 };
    *(uint2*)&o[i] = r;
}

// row sum of fp16 E -> rinv (1/sum); reads 2KB/row, writes 4B/row
__global__ void rowsum_rinv(const __half* __restrict__ Eh, float* __restrict__ rinv) {
    const int q = blockIdx.x, b = blockIdx.y, t = threadIdx.x;
    const uint2 v = ((const uint2*)(Eh + ((long)(b * SQ + q)) * SK))[t];
    __half2 h0 = *(__half2*)&v.x, h1 = *(__half2*)&v.y;
    float s = __low2float(h0) + __high2float(h0) + __low2float(h1) + __high2float(h1);

    __shared__ float red[256];
    red[t] = s;
    __syncthreads();
#pragma unroll
    for (int o = 128; o > 0; o >>= 1) {
        if (t < o) red[t] += red[t + o];
        __syncthreads();
    }
    if (t == 0) rinv[b * SQ + q] = 1.0f / red[0];
}

// write all 8 fp32 prob replicas from fp16 E + rinv (pure HBM, overlaps final GEMM)
__global__ void replicate8(const __half* __restrict__ Eh, const float* __restrict__ rinv,
                           float* __restrict__ out_att) {
    const int q = blockIdx.x, b = blockIdx.y, t = threadIdx.x;
    const float r = rinv[b * SQ + q];
    const uint2 e = ((const uint2*)(Eh + ((long)(b * SQ + q)) * SK))[t];
    __half2 h0 = *(__half2*)&e.x, h1 = *(__half2*)&e.y;
    float4 v;
    v.x = __low2float(h0) * r;  v.y = __high2float(h0) * r;
    v.z = __low2float(h1) * r;  v.w = __high2float(h1) * r;
#pragma unroll
    for (int h = 0; h < NH; h++)
        ((float4*)(out_att + (((long)(b * NH + h) * SQ) + q) * SK))[t] = v;
}

// ================================================================================
// launch
// ================================================================================
extern "C" void kernel_launch(void* const* d_in, const int* in_sizes, int n_in,
                              void* d_out, int out_size) {
    const float* Q    = (const float*)d_in[0];
    const float* K    = (const float*)d_in[1];
    const float* V    = (const float*)d_in[2];
    const int*   mask = (const int*)  d_in[3];
    const float* Wq   = (const float*)d_in[4];
    const float* bq   = (const float*)d_in[5];
    const float* Wk   = (const float*)d_in[6];
    const float* bk   = (const float*)d_in[7];
    const float* Wv   = (const float*)d_in[8];
    const float* bv   = (const float*)d_in[9];
    const float* Wl   = (const float*)d_in[10];
    const float* bl   = (const float*)d_in[11];

    __half *Qh, *Kh, *Vh, *Wqh, *Wkh, *Wvh, *Mh, *Km, *VWt, *Eh, *wleT, *wcT, *wcP;
    float *rs, *bc, *wqbk, *wkbq, *av, *bvv, *cs, *zs;
    cudaGetSymbolAddress((void**)&Qh,    g_Qh);
    cudaGetSymbolAddress((void**)&Kh,    g_Kh);
    cudaGetSymbolAddress((void**)&Vh,    g_Vh);
    cudaGetSymbolAddress((void**)&Wqh,   g_Wqh);
    cudaGetSymbolAddress((void**)&Wkh,   g_Wkh);
    cudaGetSymbolAddress((void**)&Wvh,   g_Wvh);
    cudaGetSymbolAddress((void**)&Mh,    g_M);
    cudaGetSymbolAddress((void**)&Km,    g_Km);
    cudaGetSymbolAddress((void**)&VWt,   g_VWt);
    cudaGetSymbolAddress((void**)&Eh,    g_Eh);
    cudaGetSymbolAddress((void**)&rs,    g_rs);
    cudaGetSymbolAddress((void**)&wleT,  g_WleT);
    cudaGetSymbolAddress((void**)&wcT,   g_WcT);
    cudaGetSymbolAddress((void**)&wcP,   g_WcP);
    cudaGetSymbolAddress((void**)&bc,    g_bc);
    cudaGetSymbolAddress((void**)&wqbk,  g_wqbk);
    cudaGetSymbolAddress((void**)&wkbq,  g_wkbq);
    cudaGetSymbolAddress((void**)&av,    g_a);
    cudaGetSymbolAddress((void**)&bvv,   g_b);
    cudaGetSymbolAddress((void**)&cs,    g_c);
    cudaGetSymbolAddress((void**)&zs,    g_zero);

    float* Yout = (float*)d_out;
    const long YSIZE = (long)BATCH * SQ * DM;
    const long ASIZE = (long)BATCH * NH * SQ * SK;
    float* out_att = ((long)out_size >= YSIZE + ASIZE) ? (Yout + YSIZE) : nullptr;
    const float inv_scale = 1.0f / sqrtf((float)DM);

    cudaFuncSetAttribute(gemm_h<0,0>, cudaFuncAttributeMaxDynamicSharedMemorySize, GEMM_SMEM);
    cudaFuncSetAttribute(gemm_h<0,1>, cudaFuncAttributeMaxDynamicSharedMemorySize, GEMM_SMEM);
    cudaFuncSetAttribute(gemm_h<1,0>, cudaFuncAttributeMaxDynamicSharedMemorySize, GEMM_SMEM);
    cudaFuncSetAttribute(gemm_h<2,1>, cudaFuncAttributeMaxDynamicSharedMemorySize, GEMM_SMEM);

    // lazily-created side streams + events (capture-safe; no device allocs)
    static cudaStream_t sA = nullptr, sB = nullptr;
    static cudaEvent_t  e0 = nullptr, eKc = nullptr, eR = nullptr, eVp = nullptr,
                        eK = nullptr, eA = nullptr, eN = nullptr, eB = nullptr;
    if (!sA) {
        cudaStreamCreateWithFlags(&sA, cudaStreamNonBlocking);
        cudaStreamCreateWithFlags(&sB, cudaStreamNonBlocking);
        cudaEventCreateWithFlags(&e0,  cudaEventDisableTiming);
        cudaEventCreateWithFlags(&eKc, cudaEventDisableTiming);
        cudaEventCreateWithFlags(&eR,  cudaEventDisableTiming);
        cudaEventCreateWithFlags(&eVp, cudaEventDisableTiming);
        cudaEventCreateWithFlags(&eK,  cudaEventDisableTiming);
        cudaEventCreateWithFlags(&eA,  cudaEventDisableTiming);
        cudaEventCreateWithFlags(&eN,  cudaEventDisableTiming);
        cudaEventCreateWithFlags(&eB,  cudaEventDisableTiming);
    }
    const bool ok = (sA && sB && e0 && eKc && eR && eVp && eK && eA && eN && eB);
    cudaStream_t wA = ok ? sA : (cudaStream_t)0;   // weight/K tensor leg
    cudaStream_t wB = ok ? sB : (cudaStream_t)0;   // helpers / V-prep / replicate leg

    const int NBIG = (BATCH * SQ * DM) / 1024;
    const int NSML = (DM * DM) / 1024;

    if (ok) {
        cudaEventRecord(e0, 0);
        cudaStreamWaitEvent(wA, e0, 0);
        cudaStreamWaitEvent(wB, e0, 0);
    }

    // ---- stream0: K convert first (gates Km), then Q convert ----
    f32_to_f16<<<NBIG, 256>>>(K, Kh);
    if (ok) cudaEventRecord(eKc, 0);
    f32_to_f16<<<NBIG, 256>>>(Q, Qh);

    // ---- streamB: rank-1 precomputes, then V-prep small kernels ----
    dot512<<<1, 256, 0, wB>>>(bq, bk, cs);
    vecdot512<<<DM, 128, 0, wB>>>(Wq, bk, wqbk);
    vecdot512<<<DM, 128, 0, wB>>>(Wk, bq, wkbq);
    rowdot<<<BATCH * SQ, 128, 0, wB>>>(Q, wqbk, cs, av, inv_scale);
    rowdot<<<BATCH * SK, 128, 0, wB>>>(K, wkbq, zs, bvv, inv_scale);
    if (ok) cudaEventRecord(eR, wB);
    f32_to_f16<<<NBIG, 256, 0, wB>>>(V, Vh);
    f32_to_f16<<<NSML, 256, 0, wB>>>(Wv, Wvh);
    wl_sumT_tiled<<<dim3(16, 16), dim3(32, 8), 0, wB>>>(Wl, wleT);
    bc_kernel<<<DM, 256, 0, wB>>>(bl, bv, wleT, bc);
    if (ok) cudaEventRecord(eVp, wB);

    // ---- streamA: M~ then Km (full batch), then WcT / VWt ----
    f32_to_f16<<<NSML, 256, 0, wA>>>(Wq, Wqh);
    f32_to_f16<<<NSML, 256, 0, wA>>>(Wk, Wkh);
    gemm_h<0,1><<<dim3(DM / BN, DM / BM, 4), 256, GEMM_SMEM, wA>>>(
        Wqh, Wkh, wcP, 128, 128, 128, (long)DM * DM,
        nullptr, nullptr, 0.f, 0, 0, DM, DM, nullptr, nullptr);
    reduce4<<<DM * DM / 1024, 256, 0, wA>>>(wcP, Mh);
    if (ok) cudaStreamWaitEvent(wA, eKc, 0);
    gemm_h<0,1><<<dim3(DM / BN, (BATCH * SK) / BM, 1), 256, GEMM_SMEM, wA>>>(
        Kh, Mh, Km, DM, 0, 0, 0, nullptr, nullptr, 0.f, 0, 0, DM, DM, nullptr, nullptr);
    if (ok) cudaEventRecord(eK, wA);
    if (ok) cudaStreamWaitEvent(wA, eVp, 0);
    gemm_h<2,1><<<dim3(DM / BN, DM / BM, 4), 256, GEMM_SMEM, wA>>>(
        Wvh, wleT, wcP, 128, 128, 128, (long)DM * DM,
        nullptr, nullptr, 0.f, DM, 0, DM, DM, nullptr, nullptr);
    reduce4<<<DM * DM / 1024, 256, 0, wA>>>(wcP, wcT);
    gemm_h<2,1><<<dim3(DM / BN, (BATCH * SK) / BM, 1), 256, GEMM_SMEM, wA>>>(
        Vh, wcT, VWt, DM, 0, 0, 0, nullptr, nullptr, 0.f, SK, (long)DM * SK, DM, DM,
        nullptr, nullptr);
    if (ok) cudaEventRecord(eA, wA);

    // ---- stream0: E = fp16(exp(scores)) fused; then tiny row-sum ----
    if (ok) { cudaStreamWaitEvent(0, eK, 0); cudaStreamWaitEvent(0, eR, 0); }
    gemm_h<1,0><<<dim3(SK / BN, SQ / BM, BATCH), 256, GEMM_SMEM>>>(
        Qh, Km, Eh, DM, (long)SQ * DM, (long)SK * DM, (long)SQ * SK,
        nullptr, mask, inv_scale, 0, 0, DM, DM, av, bvv);
    rowsum_rinv<<<dim3(SQ, BATCH), 256>>>(Eh, rs);

    // ---- fork replicate leg (8 fp32 replicas from fp16 E + rinv) ----
    if (out_att) {
        if (ok) {
            cudaEventRecord(eN, 0);
            cudaStreamWaitEvent(wB, eN, 0);
        }
        replicate8<<<dim3(SQ, BATCH), 256, 0, wB>>>(Eh, rs, out_att);
        if (ok) cudaEventRecord(eB, wB);
    }

    // ---- join leg A; final GEMM: Y = (E @ VW) * rinv + bc ----
    if (ok) cudaStreamWaitEvent(0, eA, 0);
    gemm_h<0,0><<<dim3(DM / BN, SQ / BM, BATCH), 256, GEMM_SMEM>>>(
        Eh, VWt, Yout, SK, (long)SQ * SK, (long)DM * SK, (long)SQ * DM,
        bc, nullptr, 0.f, 0, 0, SK, SK, rs, nullptr);

    // ---- join replicate leg ----
    if (out_att && ok) cudaStreamWaitEvent(0, eB, 0);
}